// round 4
// baseline (speedup 1.0000x reference)
#include <cuda_runtime.h>
#include <math.h>
#include <stdint.h>

// ---------------------------------------------------------------------------
// Problem constants
// ---------------------------------------------------------------------------
#define BATCH 8
#define CCH   384        // channels
#define HH    56
#define WW    56
#define NTOK  (BATCH*HH*WW)   // 25088 tokens
#define QKVC  (3*CCH)         // 1152
#define HIDN  1536
#define NHEAD 12
#define HDIM  32
#define EPSLN 1e-5f

// ---------------------------------------------------------------------------
// Scratch (static device globals: no allocation at kernel_launch time)
// ---------------------------------------------------------------------------
__device__ float g_xn [(size_t)NTOK*CCH];   // LN1 output, token-major [N,C]
__device__ float g_xpT[(size_t)NTOK*CCH];   // raw transposed x, [N,C]
__device__ float g_qkv[(size_t)NTOK*QKVC];  // [N,1152]
__device__ float g_att[(size_t)NTOK*CCH];   // attention out + xn residual
__device__ float g_xpb[(size_t)NTOK*CCH];   // after proj residual
__device__ float g_x2 [(size_t)NTOK*CCH];   // LN2 output
__device__ float g_h  [(size_t)NTOK*HIDN];  // MLP hidden
__device__ float g_xf [(size_t)NTOK*CCH];   // final token-major result

// ---------------------------------------------------------------------------
// LN1: x [B,C,H,W] -> xn [N,C] (normed) and xpT [N,C] (raw transpose)
// One block handles 28 consecutive-x tokens of one (b,y) row. grid (2,56,8).
// ---------------------------------------------------------------------------
__global__ __launch_bounds__(256) void ln1_kernel(
    const float* __restrict__ x, const float* __restrict__ gam,
    const float* __restrict__ bet, float* __restrict__ xn,
    float* __restrict__ xpT)
{
    const int TPB = 28;                 // tokens per block
    __shared__ float s[CCH*TPB];        // [c][t], 43008 B
    __shared__ float ps[9*TPB];
    __shared__ float pq[9*TPB];
    __shared__ float s_mean[TPB];
    __shared__ float s_rstd[TPB];

    int tid = threadIdx.x;
    int x0  = blockIdx.x * TPB;
    int y   = blockIdx.y;
    int b   = blockIdx.z;

    // coalesced load: consecutive tid -> consecutive x column
    for (int idx = tid; idx < CCH*TPB; idx += 256) {
        int c = idx / TPB;
        int t = idx % TPB;
        s[idx] = x[(((size_t)b*CCH + c)*HH + y)*WW + x0 + t];
    }
    __syncthreads();

    if (tid < 9*TPB) {
        int sub = tid / TPB;   // 0..8
        int t   = tid % TPB;
        float sm = 0.f, sq = 0.f;
        for (int c = sub; c < CCH; c += 9) {
            float v = s[c*TPB + t];
            sm += v; sq += v*v;
        }
        ps[sub*TPB + t] = sm;
        pq[sub*TPB + t] = sq;
    }
    __syncthreads();
    if (tid < TPB) {
        float sm = 0.f, sq = 0.f;
        #pragma unroll
        for (int sub = 0; sub < 9; sub++) { sm += ps[sub*TPB + tid]; sq += pq[sub*TPB + tid]; }
        float mu  = sm * (1.f/CCH);
        float var = sq * (1.f/CCH) - mu*mu;
        s_mean[tid] = mu;
        s_rstd[tid] = rsqrtf(var + EPSLN);
    }
    __syncthreads();

    // coalesced writes: idx = t*C + c, consecutive c contiguous in [N,C]
    for (int idx = tid; idx < CCH*TPB; idx += 256) {
        int t = idx / CCH;
        int c = idx % CCH;
        float v = s[c*TPB + t];
        size_t n = (size_t)b*(HH*WW) + (size_t)y*WW + (x0 + t);
        xpT[n*CCH + c] = v;
        xn [n*CCH + c] = (v - s_mean[t]) * s_rstd[t] * gam[c] + bet[c];
    }
}

// ---------------------------------------------------------------------------
// Generic fp32 GEMM:  C[M,Nc] = A[M,K] @ Bw[Nc,K]^T  (+bias)(+gelu|+residual)
// BM=BN=128, BK=16, 256 threads, 8x8 register tile per thread.
// mode: 0 = bias-only(if bias), 1 = bias+exact GELU, 2 = bias+residual
// M % 128 == 0, Nc % 128 == 0, K % 16 == 0 guaranteed by the shapes here.
// ---------------------------------------------------------------------------
__global__ __launch_bounds__(256) void gemm_nt_kernel(
    const float* __restrict__ A, const float* __restrict__ Bw,
    const float* __restrict__ bias, const float* __restrict__ resid,
    float* __restrict__ C, int M, int Nc, int K, int mode)
{
    const int BM = 128, BN = 128, BK = 16;
    __shared__ float As[BK][BM];
    __shared__ float Bs[BK][BN];

    int tid = threadIdx.x;
    int m0 = blockIdx.x * BM;
    int n0 = blockIdx.y * BN;
    int tr = tid >> 4;   // 0..15 (M direction)
    int tc = tid & 15;   // 0..15 (N direction)

    const float* Aptr = A  + (size_t)m0 * K;
    const float* Bptr = Bw + (size_t)n0 * K;

    float acc[8][8];
    #pragma unroll
    for (int i = 0; i < 8; i++)
        #pragma unroll
        for (int j = 0; j < 8; j++) acc[i][j] = 0.f;

    for (int k0 = 0; k0 < K; k0 += BK) {
        // 128 rows x 16 k = 512 float4 for each of A and B tiles
        #pragma unroll
        for (int it = 0; it < 2; it++) {
            int f   = tid + it * 256;      // 0..511
            int row = f >> 2;
            int kc  = (f & 3) << 2;
            float4 va = *(const float4*)(Aptr + (size_t)row * K + k0 + kc);
            As[kc+0][row] = va.x; As[kc+1][row] = va.y;
            As[kc+2][row] = va.z; As[kc+3][row] = va.w;
            float4 vb = *(const float4*)(Bptr + (size_t)row * K + k0 + kc);
            Bs[kc+0][row] = vb.x; Bs[kc+1][row] = vb.y;
            Bs[kc+2][row] = vb.z; Bs[kc+3][row] = vb.w;
        }
        __syncthreads();

        #pragma unroll
        for (int k = 0; k < BK; k++) {
            float a[8], b[8];
            *(float4*)&a[0] = *(const float4*)&As[k][tr*8];
            *(float4*)&a[4] = *(const float4*)&As[k][tr*8 + 4];
            *(float4*)&b[0] = *(const float4*)&Bs[k][tc*8];
            *(float4*)&b[4] = *(const float4*)&Bs[k][tc*8 + 4];
            #pragma unroll
            for (int i = 0; i < 8; i++)
                #pragma unroll
                for (int j = 0; j < 8; j++)
                    acc[i][j] = fmaf(a[i], b[j], acc[i][j]);
        }
        __syncthreads();
    }

    #pragma unroll
    for (int i = 0; i < 8; i++) {
        size_t m = (size_t)m0 + tr*8 + i;
        #pragma unroll
        for (int j = 0; j < 8; j++) {
            int n = n0 + tc*8 + j;
            float v = acc[i][j];
            if (bias) v += bias[n];
            if (mode == 1) {
                // exact GELU (erf form), matches jax approximate=False
                v = 0.5f * v * (1.0f + erff(v * 0.7071067811865476f));
            } else if (mode == 2) {
                v += resid[m * Nc + n];
            }
            C[m * Nc + n] = v;
        }
    }
}

// ---------------------------------------------------------------------------
// Multi-dilation 3x3 local attention. One block per token, one warp per head.
// OOB neighbors contribute logit exactly 0 (zero-padded unfold) and v = 0.
// Output: att[n,c] = attn_out + xn[n,c]   (fused "a = a + xn" residual)
// ---------------------------------------------------------------------------
__global__ __launch_bounds__(384) void attn_kernel(
    const float* __restrict__ qkv, const float* __restrict__ xn,
    float* __restrict__ att)
{
    int n    = blockIdx.x;
    int b    = n / (HH*WW);
    int rem  = n % (HH*WW);
    int y    = rem / WW;
    int xx   = rem % WW;
    int w    = threadIdx.x >> 5;      // head 0..11
    int lane = threadIdx.x & 31;      // dim within head

    int dil = (w >> 2) + 1;           // DILS = (1,2,3)
    int c0  = w * HDIM;               // = branch*128 + head_in_branch*32

    const float scale = 0.17677669529663687f;   // 32^-0.5

    float q = qkv[(size_t)n*QKVC + c0 + lane];

    float logit[9];
    int   nn[9];
    #pragma unroll
    for (int e = 0; e < 9; e++) {
        int ki = e / 3, kj = e % 3;
        int ny = y  + (ki - 1) * dil;
        int nx = xx + (kj - 1) * dil;
        bool ok = ((unsigned)ny < HH) && ((unsigned)nx < WW);
        int tok = ok ? (b*(HH*WW) + ny*WW + nx) : -1;
        nn[e] = tok;
        float p = 0.f;
        if (ok) p = q * qkv[(size_t)tok*QKVC + CCH + c0 + lane];
        #pragma unroll
        for (int off = 16; off > 0; off >>= 1)
            p += __shfl_xor_sync(0xffffffffu, p, off);
        logit[e] = p * scale;         // OOB -> exactly 0, still in softmax
    }

    float mx = logit[0];
    #pragma unroll
    for (int e = 1; e < 9; e++) mx = fmaxf(mx, logit[e]);
    float pe[9];
    float sum = 0.f;
    #pragma unroll
    for (int e = 0; e < 9; e++) { pe[e] = __expf(logit[e] - mx); sum += pe[e]; }
    float inv = 1.f / sum;

    float o = 0.f;
    #pragma unroll
    for (int e = 0; e < 9; e++) {
        if (nn[e] >= 0)
            o = fmaf(pe[e] * inv,
                     qkv[(size_t)nn[e]*QKVC + 2*CCH + c0 + lane], o);
    }

    att[(size_t)n*CCH + c0 + lane] = o + xn[(size_t)n*CCH + c0 + lane];
}

// ---------------------------------------------------------------------------
// LN2 over token-major [N,C]. One block (128 threads) per token.
// ---------------------------------------------------------------------------
__global__ __launch_bounds__(128) void ln2_kernel(
    const float* __restrict__ in, const float* __restrict__ gam,
    const float* __restrict__ bet, float* __restrict__ out)
{
    __shared__ float rs[4], rq[4];
    __shared__ float s_mu, s_rstd;
    int n   = blockIdx.x;
    int tid = threadIdx.x;
    const float* row = in + (size_t)n * CCH;

    float v0 = row[tid];
    float v1 = row[tid + 128];
    float v2 = row[tid + 256];
    float sm = v0 + v1 + v2;
    float sq = v0*v0 + v1*v1 + v2*v2;
    #pragma unroll
    for (int off = 16; off > 0; off >>= 1) {
        sm += __shfl_xor_sync(0xffffffffu, sm, off);
        sq += __shfl_xor_sync(0xffffffffu, sq, off);
    }
    int wid = tid >> 5, lane = tid & 31;
    if (lane == 0) { rs[wid] = sm; rq[wid] = sq; }
    __syncthreads();
    if (tid == 0) {
        float tsm = rs[0]+rs[1]+rs[2]+rs[3];
        float tsq = rq[0]+rq[1]+rq[2]+rq[3];
        float mu  = tsm * (1.f/CCH);
        float var = tsq * (1.f/CCH) - mu*mu;
        s_mu = mu;
        s_rstd = rsqrtf(var + EPSLN);
    }
    __syncthreads();
    float mu = s_mu, rstd = s_rstd;
    float* orow = out + (size_t)n * CCH;
    orow[tid      ] = (v0 - mu) * rstd * gam[tid      ] + bet[tid      ];
    orow[tid + 128] = (v1 - mu) * rstd * gam[tid + 128] + bet[tid + 128];
    orow[tid + 256] = (v2 - mu) * rstd * gam[tid + 256] + bet[tid + 256];
}

// ---------------------------------------------------------------------------
// Final transpose: [B, HW, C] -> [B, C, HW]  (32x32 tiles through shared)
// ---------------------------------------------------------------------------
__global__ __launch_bounds__(256) void transpose_out_kernel(
    const float* __restrict__ in, float* __restrict__ out)
{
    __shared__ float tile[32][33];
    int b  = blockIdx.z;
    int c0 = blockIdx.x * 32;   // channel tile
    int s0 = blockIdx.y * 32;   // spatial tile
    int tx = threadIdx.x;       // 0..31
    int ty = threadIdx.y;       // 0..7

    #pragma unroll
    for (int rr = ty; rr < 32; rr += 8)
        tile[rr][tx] = in[((size_t)b*(HH*WW) + s0 + rr)*CCH + c0 + tx];
    __syncthreads();
    #pragma unroll
    for (int rr = ty; rr < 32; rr += 8)
        out[((size_t)b*CCH + c0 + rr)*(HH*WW) + s0 + tx] = tile[tx][rr];
}

// ---------------------------------------------------------------------------
// kernel_launch
// ---------------------------------------------------------------------------
extern "C" void kernel_launch(void* const* d_in, const int* in_sizes, int n_in,
                              void* d_out, int out_size)
{
    const float* x      = (const float*)d_in[0];
    const float* qkv_w  = (const float*)d_in[1];
    const float* proj_w = (const float*)d_in[2];
    const float* proj_b = (const float*)d_in[3];
    const float* n1_g   = (const float*)d_in[4];
    const float* n1_b   = (const float*)d_in[5];
    const float* n2_g   = (const float*)d_in[6];
    const float* n2_b   = (const float*)d_in[7];
    const float* fc1_w  = (const float*)d_in[8];
    const float* fc1_b  = (const float*)d_in[9];
    const float* fc2_w  = (const float*)d_in[10];
    const float* fc2_b  = (const float*)d_in[11];
    float* out = (float*)d_out;

    float *xn, *xpT, *qkv, *att, *xpb, *x2, *h, *xf;
    cudaGetSymbolAddress((void**)&xn,  g_xn);
    cudaGetSymbolAddress((void**)&xpT, g_xpT);
    cudaGetSymbolAddress((void**)&qkv, g_qkv);
    cudaGetSymbolAddress((void**)&att, g_att);
    cudaGetSymbolAddress((void**)&xpb, g_xpb);
    cudaGetSymbolAddress((void**)&x2,  g_x2);
    cudaGetSymbolAddress((void**)&h,   g_h);
    cudaGetSymbolAddress((void**)&xf,  g_xf);

    // 1. LN1 + NCHW->NHWC transpose
    ln1_kernel<<<dim3(2, HH, BATCH), 256>>>(x, n1_g, n1_b, xn, xpT);

    // 2. QKV 1x1 conv: [N,384] @ [1152,384]^T, no bias
    gemm_nt_kernel<<<dim3(NTOK/128, QKVC/128), 256>>>(
        xn, qkv_w, nullptr, nullptr, qkv, NTOK, QKVC, CCH, 0);

    // 3. Multi-dilation local attention + xn residual
    attn_kernel<<<NTOK, 384>>>(qkv, xn, att);

    // 4. proj + bias + residual(raw transposed x)
    gemm_nt_kernel<<<dim3(NTOK/128, CCH/128), 256>>>(
        att, proj_w, proj_b, xpT, xpb, NTOK, CCH, CCH, 2);

    // 5. LN2
    ln2_kernel<<<NTOK, 128>>>(xpb, n2_g, n2_b, x2);

    // 6. fc1 + bias + exact GELU
    gemm_nt_kernel<<<dim3(NTOK/128, HIDN/128), 256>>>(
        x2, fc1_w, fc1_b, nullptr, h, NTOK, HIDN, CCH, 1);

    // 7. fc2 + bias + residual
    gemm_nt_kernel<<<dim3(NTOK/128, CCH/128), 256>>>(
        h, fc2_w, fc2_b, xpb, xf, NTOK, CCH, HIDN, 2);

    // 8. NHWC -> NCHW
    transpose_out_kernel<<<dim3(CCH/32, (HH*WW)/32, BATCH), dim3(32, 8)>>>(xf, out);
}

// round 6
// speedup vs baseline: 2.6496x; 2.6496x over previous
#include <cuda_runtime.h>
#include <math.h>
#include <stdint.h>

// ---------------------------------------------------------------------------
// Problem constants
// ---------------------------------------------------------------------------
#define BATCH 8
#define CCH   384
#define HH    56
#define WW    56
#define NTOK  (BATCH*HH*WW)   // 25088
#define QKVC  (3*CCH)         // 1152
#define HIDN  1536
#define NHEAD 12
#define HDIM  32
#define EPSLN 1e-5f

// ---------------------------------------------------------------------------
// Scratch
// ---------------------------------------------------------------------------
__device__ float g_xn [(size_t)NTOK*CCH];
__device__ float g_xpT[(size_t)NTOK*CCH];
__device__ float g_qkv[(size_t)NTOK*QKVC];
__device__ float g_att[(size_t)NTOK*CCH];
__device__ float g_xpb[(size_t)NTOK*CCH];
__device__ float g_x2 [(size_t)NTOK*CCH];
__device__ float g_h  [(size_t)NTOK*HIDN];
__device__ float g_xf [(size_t)NTOK*CCH];

// ---------------------------------------------------------------------------
// helpers
// ---------------------------------------------------------------------------
__device__ __forceinline__ uint32_t smem_u32(const void* p) {
    uint32_t a;
    asm("{ .reg .u64 t; cvta.to.shared.u64 t, %1; cvt.u32.u64 %0, t; }"
        : "=r"(a) : "l"(p));
    return a;
}
__device__ __forceinline__ void cp_async16(uint32_t s, const void* g) {
    asm volatile("cp.async.cg.shared.global [%0], [%1], 16;"
                 :: "r"(s), "l"(g));
}
__device__ __forceinline__ void cp_commit() {
    asm volatile("cp.async.commit_group;" ::: "memory");
}
template<int N>
__device__ __forceinline__ void cp_wait() {
    asm volatile("cp.async.wait_group %0;" :: "n"(N) : "memory");
}
__device__ __forceinline__ uint32_t f2tf32(float v) {
    uint32_t u;
    asm("cvt.rna.tf32.f32 %0, %1;" : "=r"(u) : "f"(v));
    return u;
}
__device__ __forceinline__ void mma_tf32(float* c, const uint32_t* a,
                                         const uint32_t* b) {
    asm volatile(
        "mma.sync.aligned.m16n8k8.row.col.f32.tf32.tf32.f32 "
        "{%0,%1,%2,%3}, {%4,%5,%6,%7}, {%8,%9}, {%0,%1,%2,%3};"
        : "+f"(c[0]), "+f"(c[1]), "+f"(c[2]), "+f"(c[3])
        : "r"(a[0]), "r"(a[1]), "r"(a[2]), "r"(a[3]),
          "r"(b[0]), "r"(b[1]));
}

// ---------------------------------------------------------------------------
// tf32 mma.sync GEMM:  C[M,Nc] = A[M,K] @ Bw[Nc,K]^T  (+bias)(+gelu|+resid)
// CTA tile 128x128, BK=32, 2-stage cp.async double buffer.
// 256 threads = 8 warps as 2(M)x4(N); warp tile 64x32 via m16n8k8.
// Smem row stride 36 floats: LDS banks (4r+c) all distinct, rows 144B aligned.
// mode: 0 = plain, 1 = bias+erf GELU, 2 = bias+residual
// ---------------------------------------------------------------------------
#define ASTRIDE 36
#define STAGE_BYTES (128*ASTRIDE*4)        // 18432
#define GEMM_SMEM   (4*STAGE_BYTES)        // A0 A1 B0 B1 = 73728

__global__ __launch_bounds__(256, 2) void gemm_tc_kernel(
    const float* __restrict__ A, const float* __restrict__ Bw,
    const float* __restrict__ bias, const float* __restrict__ resid,
    float* __restrict__ C, int M, int Nc, int K, int mode)
{
    extern __shared__ char smem[];
    uint32_t sb = smem_u32(smem);

    int tid    = threadIdx.x;
    int wid    = tid >> 5;
    int lane   = tid & 31;
    int warp_m = wid & 1;          // 0..1 -> 64-row halves
    int warp_n = wid >> 1;         // 0..3 -> 32-col quarters
    int m0     = blockIdx.x * 128;
    int n0     = blockIdx.y * 128;

    const float* Ab = A  + (size_t)m0 * K;
    const float* Bb = Bw + (size_t)n0 * K;
    const int NCH = K >> 5;

    int gid = lane >> 2;           // groupID 0..7
    int tig = lane & 3;            // thread-in-group 0..3

    float acc[4][4][4];
    #pragma unroll
    for (int i = 0; i < 4; i++)
        #pragma unroll
        for (int j = 0; j < 4; j++)
            #pragma unroll
            for (int q = 0; q < 4; q++) acc[i][j][q] = 0.f;

    // stage bases: A0, A1, B0, B1
    auto load_chunk = [&](int kc, int st) {
        int k0 = kc << 5;
        uint32_t as = sb + st * STAGE_BYTES;
        uint32_t bs = sb + (2 + st) * STAGE_BYTES;
        #pragma unroll
        for (int r = 0; r < 4; r++) {
            int idx = tid + r * 256;          // 0..1023
            int row = idx >> 3;
            int g   = idx & 7;
            uint32_t doff = (uint32_t)(row * (ASTRIDE*4) + g * 16);
            cp_async16(as + doff, Ab + (size_t)row * K + k0 + g * 4);
            cp_async16(bs + doff, Bb + (size_t)row * K + k0 + g * 4);
        }
        cp_commit();
    };

    load_chunk(0, 0);

    for (int i = 0; i < NCH; i++) {
        int st = i & 1;
        if (i + 1 < NCH) {
            load_chunk(i + 1, st ^ 1);
            cp_wait<1>();
        } else {
            cp_wait<0>();
        }
        __syncthreads();

        const float* Asf = (const float*)(smem + st * STAGE_BYTES);
        const float* Bsf = (const float*)(smem + (2 + st) * STAGE_BYTES);

        #pragma unroll
        for (int ks = 0; ks < 4; ks++) {
            int k0 = ks << 3;
            uint32_t afr[4][4];
            #pragma unroll
            for (int mf = 0; mf < 4; mf++) {
                int r = warp_m * 64 + mf * 16 + gid;
                afr[mf][0] = f2tf32(Asf[ r      * ASTRIDE + k0 + tig    ]);
                afr[mf][1] = f2tf32(Asf[(r + 8) * ASTRIDE + k0 + tig    ]);
                afr[mf][2] = f2tf32(Asf[ r      * ASTRIDE + k0 + tig + 4]);
                afr[mf][3] = f2tf32(Asf[(r + 8) * ASTRIDE + k0 + tig + 4]);
            }
            uint32_t bfr[4][2];
            #pragma unroll
            for (int nf = 0; nf < 4; nf++) {
                int nn = warp_n * 32 + nf * 8 + gid;
                bfr[nf][0] = f2tf32(Bsf[nn * ASTRIDE + k0 + tig    ]);
                bfr[nf][1] = f2tf32(Bsf[nn * ASTRIDE + k0 + tig + 4]);
            }
            #pragma unroll
            for (int mf = 0; mf < 4; mf++)
                #pragma unroll
                for (int nf = 0; nf < 4; nf++)
                    mma_tf32(acc[mf][nf], afr[mf], bfr[nf]);
        }
        __syncthreads();
    }

    // ---------------- epilogue ----------------
    #pragma unroll
    for (int mf = 0; mf < 4; mf++) {
        #pragma unroll
        for (int nf = 0; nf < 4; nf++) {
            int row = m0 + warp_m * 64 + mf * 16 + gid;
            int col = n0 + warp_n * 32 + nf * 8 + tig * 2;
            #pragma unroll
            for (int half = 0; half < 2; half++) {
                size_t rr = (size_t)(row + half * 8);
                float v0 = acc[mf][nf][half * 2 + 0];
                float v1 = acc[mf][nf][half * 2 + 1];
                if (bias) { v0 += bias[col]; v1 += bias[col + 1]; }
                if (mode == 1) {
                    v0 = 0.5f * v0 * (1.0f + erff(v0 * 0.7071067811865476f));
                    v1 = 0.5f * v1 * (1.0f + erff(v1 * 0.7071067811865476f));
                } else if (mode == 2) {
                    float2 rv = *(const float2*)&resid[rr * Nc + col];
                    v0 += rv.x; v1 += rv.y;
                }
                float2 o; o.x = v0; o.y = v1;
                *(float2*)&C[rr * Nc + col] = o;
            }
        }
    }
}

// ---------------------------------------------------------------------------
// LN1: x [B,C,H,W] -> xn [N,C] + xpT [N,C]
// ---------------------------------------------------------------------------
__global__ __launch_bounds__(256) void ln1_kernel(
    const float* __restrict__ x, const float* __restrict__ gam,
    const float* __restrict__ bet, float* __restrict__ xn,
    float* __restrict__ xpT)
{
    const int TPB = 28;
    __shared__ float s[CCH*TPB];
    __shared__ float ps[9*TPB];
    __shared__ float pq[9*TPB];
    __shared__ float s_mean[TPB];
    __shared__ float s_rstd[TPB];

    int tid = threadIdx.x;
    int x0  = blockIdx.x * TPB;
    int y   = blockIdx.y;
    int b   = blockIdx.z;

    for (int idx = tid; idx < CCH*TPB; idx += 256) {
        int c = idx / TPB;
        int t = idx % TPB;
        s[idx] = x[(((size_t)b*CCH + c)*HH + y)*WW + x0 + t];
    }
    __syncthreads();

    if (tid < 9*TPB) {
        int sub = tid / TPB;
        int t   = tid % TPB;
        float sm = 0.f, sq = 0.f;
        for (int c = sub; c < CCH; c += 9) {
            float v = s[c*TPB + t];
            sm += v; sq += v*v;
        }
        ps[sub*TPB + t] = sm;
        pq[sub*TPB + t] = sq;
    }
    __syncthreads();
    if (tid < TPB) {
        float sm = 0.f, sq = 0.f;
        #pragma unroll
        for (int sub = 0; sub < 9; sub++) { sm += ps[sub*TPB + tid]; sq += pq[sub*TPB + tid]; }
        float mu  = sm * (1.f/CCH);
        float var = sq * (1.f/CCH) - mu*mu;
        s_mean[tid] = mu;
        s_rstd[tid] = rsqrtf(var + EPSLN);
    }
    __syncthreads();

    for (int idx = tid; idx < CCH*TPB; idx += 256) {
        int t = idx / CCH;
        int c = idx % CCH;
        float v = s[c*TPB + t];
        size_t n = (size_t)b*(HH*WW) + (size_t)y*WW + (x0 + t);
        xpT[n*CCH + c] = v;
        xn [n*CCH + c] = (v - s_mean[t]) * s_rstd[t] * gam[c] + bet[c];
    }
}

// ---------------------------------------------------------------------------
// Multi-dilation 3x3 local attention + fused "+xn" residual
// ---------------------------------------------------------------------------
__global__ __launch_bounds__(384) void attn_kernel(
    const float* __restrict__ qkv, const float* __restrict__ xn,
    float* __restrict__ att)
{
    int n    = blockIdx.x;
    int b    = n / (HH*WW);
    int rem  = n % (HH*WW);
    int y    = rem / WW;
    int xx   = rem % WW;
    int w    = threadIdx.x >> 5;
    int lane = threadIdx.x & 31;

    int dil = (w >> 2) + 1;
    int c0  = w * HDIM;

    const float scale = 0.17677669529663687f;

    float q = qkv[(size_t)n*QKVC + c0 + lane];

    float logit[9];
    int   nn[9];
    #pragma unroll
    for (int e = 0; e < 9; e++) {
        int ki = e / 3, kj = e % 3;
        int ny = y  + (ki - 1) * dil;
        int nx = xx + (kj - 1) * dil;
        bool ok = ((unsigned)ny < HH) && ((unsigned)nx < WW);
        int tok = ok ? (b*(HH*WW) + ny*WW + nx) : -1;
        nn[e] = tok;
        float p = 0.f;
        if (ok) p = q * qkv[(size_t)tok*QKVC + CCH + c0 + lane];
        #pragma unroll
        for (int off = 16; off > 0; off >>= 1)
            p += __shfl_xor_sync(0xffffffffu, p, off);
        logit[e] = p * scale;
    }

    float mx = logit[0];
    #pragma unroll
    for (int e = 1; e < 9; e++) mx = fmaxf(mx, logit[e]);
    float pe[9];
    float sum = 0.f;
    #pragma unroll
    for (int e = 0; e < 9; e++) { pe[e] = __expf(logit[e] - mx); sum += pe[e]; }
    float inv = 1.f / sum;

    float o = 0.f;
    #pragma unroll
    for (int e = 0; e < 9; e++) {
        if (nn[e] >= 0)
            o = fmaf(pe[e] * inv,
                     qkv[(size_t)nn[e]*QKVC + 2*CCH + c0 + lane], o);
    }

    att[(size_t)n*CCH + c0 + lane] = o + xn[(size_t)n*CCH + c0 + lane];
}

// ---------------------------------------------------------------------------
// LN2
// ---------------------------------------------------------------------------
__global__ __launch_bounds__(128) void ln2_kernel(
    const float* __restrict__ in, const float* __restrict__ gam,
    const float* __restrict__ bet, float* __restrict__ out)
{
    __shared__ float rs[4], rq[4];
    __shared__ float s_mu, s_rstd;
    int n   = blockIdx.x;
    int tid = threadIdx.x;
    const float* row = in + (size_t)n * CCH;

    float v0 = row[tid];
    float v1 = row[tid + 128];
    float v2 = row[tid + 256];
    float sm = v0 + v1 + v2;
    float sq = v0*v0 + v1*v1 + v2*v2;
    #pragma unroll
    for (int off = 16; off > 0; off >>= 1) {
        sm += __shfl_xor_sync(0xffffffffu, sm, off);
        sq += __shfl_xor_sync(0xffffffffu, sq, off);
    }
    int wid = tid >> 5, lane = tid & 31;
    if (lane == 0) { rs[wid] = sm; rq[wid] = sq; }
    __syncthreads();
    if (tid == 0) {
        float tsm = rs[0]+rs[1]+rs[2]+rs[3];
        float tsq = rq[0]+rq[1]+rq[2]+rq[3];
        float mu  = tsm * (1.f/CCH);
        float var = tsq * (1.f/CCH) - mu*mu;
        s_mu = mu;
        s_rstd = rsqrtf(var + EPSLN);
    }
    __syncthreads();
    float mu = s_mu, rstd = s_rstd;
    float* orow = out + (size_t)n * CCH;
    orow[tid      ] = (v0 - mu) * rstd * gam[tid      ] + bet[tid      ];
    orow[tid + 128] = (v1 - mu) * rstd * gam[tid + 128] + bet[tid + 128];
    orow[tid + 256] = (v2 - mu) * rstd * gam[tid + 256] + bet[tid + 256];
}

// ---------------------------------------------------------------------------
// Final transpose: [B, HW, C] -> [B, C, HW]
// ---------------------------------------------------------------------------
__global__ __launch_bounds__(256) void transpose_out_kernel(
    const float* __restrict__ in, float* __restrict__ out)
{
    __shared__ float tile[32][33];
    int b  = blockIdx.z;
    int c0 = blockIdx.x * 32;
    int s0 = blockIdx.y * 32;
    int tx = threadIdx.x;
    int ty = threadIdx.y;

    #pragma unroll
    for (int rr = ty; rr < 32; rr += 8)
        tile[rr][tx] = in[((size_t)b*(HH*WW) + s0 + rr)*CCH + c0 + tx];
    __syncthreads();
    #pragma unroll
    for (int rr = ty; rr < 32; rr += 8)
        out[((size_t)b*CCH + c0 + rr)*(HH*WW) + s0 + tx] = tile[tx][rr];
}

// ---------------------------------------------------------------------------
// kernel_launch
// ---------------------------------------------------------------------------
extern "C" void kernel_launch(void* const* d_in, const int* in_sizes, int n_in,
                              void* d_out, int out_size)
{
    const float* x      = (const float*)d_in[0];
    const float* qkv_w  = (const float*)d_in[1];
    const float* proj_w = (const float*)d_in[2];
    const float* proj_b = (const float*)d_in[3];
    const float* n1_g   = (const float*)d_in[4];
    const float* n1_b   = (const float*)d_in[5];
    const float* n2_g   = (const float*)d_in[6];
    const float* n2_b   = (const float*)d_in[7];
    const float* fc1_w  = (const float*)d_in[8];
    const float* fc1_b  = (const float*)d_in[9];
    const float* fc2_w  = (const float*)d_in[10];
    const float* fc2_b  = (const float*)d_in[11];
    float* out = (float*)d_out;

    float *xn, *xpT, *qkv, *att, *xpb, *x2, *h, *xf;
    cudaGetSymbolAddress((void**)&xn,  g_xn);
    cudaGetSymbolAddress((void**)&xpT, g_xpT);
    cudaGetSymbolAddress((void**)&qkv, g_qkv);
    cudaGetSymbolAddress((void**)&att, g_att);
    cudaGetSymbolAddress((void**)&xpb, g_xpb);
    cudaGetSymbolAddress((void**)&x2,  g_x2);
    cudaGetSymbolAddress((void**)&h,   g_h);
    cudaGetSymbolAddress((void**)&xf,  g_xf);

    cudaFuncSetAttribute(gemm_tc_kernel,
                         cudaFuncAttributeMaxDynamicSharedMemorySize, GEMM_SMEM);

    // 1. LN1 + NCHW->NHWC transpose
    ln1_kernel<<<dim3(2, HH, BATCH), 256>>>(x, n1_g, n1_b, xn, xpT);

    // 2. QKV: [N,384] @ [1152,384]^T
    gemm_tc_kernel<<<dim3(NTOK/128, QKVC/128), 256, GEMM_SMEM>>>(
        xn, qkv_w, nullptr, nullptr, qkv, NTOK, QKVC, CCH, 0);

    // 3. attention + xn residual
    attn_kernel<<<NTOK, 384>>>(qkv, xn, att);

    // 4. proj + bias + residual(x transposed)
    gemm_tc_kernel<<<dim3(NTOK/128, CCH/128), 256, GEMM_SMEM>>>(
        att, proj_w, proj_b, xpT, xpb, NTOK, CCH, CCH, 2);

    // 5. LN2
    ln2_kernel<<<NTOK, 128>>>(xpb, n2_g, n2_b, x2);

    // 6. fc1 + bias + exact GELU
    gemm_tc_kernel<<<dim3(NTOK/128, HIDN/128), 256, GEMM_SMEM>>>(
        x2, fc1_w, fc1_b, nullptr, h, NTOK, HIDN, CCH, 1);

    // 7. fc2 + bias + residual
    gemm_tc_kernel<<<dim3(NTOK/128, CCH/128), 256, GEMM_SMEM>>>(
        h, fc2_w, fc2_b, xpb, xf, NTOK, CCH, HIDN, 2);

    // 8. NHWC -> NCHW
    transpose_out_kernel<<<dim3(CCH/32, (HH*WW)/32, BATCH), dim3(32, 8)>>>(xf, out);
}

// round 7
// speedup vs baseline: 2.7145x; 1.0245x over previous
#include <cuda_runtime.h>
#include <math.h>
#include <stdint.h>

// ---------------------------------------------------------------------------
// Problem constants
// ---------------------------------------------------------------------------
#define BATCH 8
#define CCH   384
#define HH    56
#define WW    56
#define NTOK  (BATCH*HH*WW)   // 25088
#define QKVC  (3*CCH)         // 1152
#define HIDN  1536
#define NHEAD 12
#define HDIM  32
#define EPSLN 1e-5f

// ---------------------------------------------------------------------------
// Scratch
// ---------------------------------------------------------------------------
__device__ float g_xn [(size_t)NTOK*CCH];
__device__ float g_xpT[(size_t)NTOK*CCH];
__device__ float g_qkv[(size_t)NTOK*QKVC];
__device__ float g_att[(size_t)NTOK*CCH];
__device__ float g_xpb[(size_t)NTOK*CCH];
__device__ float g_x2 [(size_t)NTOK*CCH];
__device__ float g_h  [(size_t)NTOK*HIDN];
__device__ float g_xf [(size_t)NTOK*CCH];
// tf32-pre-rounded weights
__device__ float g_wq[(size_t)QKVC*CCH];
__device__ float g_wp[(size_t)CCH*CCH];
__device__ float g_w1[(size_t)HIDN*CCH];
__device__ float g_w2[(size_t)CCH*HIDN];

// ---------------------------------------------------------------------------
// helpers
// ---------------------------------------------------------------------------
__device__ __forceinline__ uint32_t smem_u32(const void* p) {
    uint32_t a;
    asm("{ .reg .u64 t; cvta.to.shared.u64 t, %1; cvt.u32.u64 %0, t; }"
        : "=r"(a) : "l"(p));
    return a;
}
__device__ __forceinline__ void cp_async16(uint32_t s, const void* g) {
    asm volatile("cp.async.cg.shared.global [%0], [%1], 16;"
                 :: "r"(s), "l"(g));
}
__device__ __forceinline__ void cp_commit() {
    asm volatile("cp.async.commit_group;" ::: "memory");
}
template<int N>
__device__ __forceinline__ void cp_wait() {
    asm volatile("cp.async.wait_group %0;" :: "n"(N) : "memory");
}
__device__ __forceinline__ float tf32r(float v) {
    uint32_t u;
    asm("cvt.rna.tf32.f32 %0, %1;" : "=r"(u) : "f"(v));
    return __uint_as_float(u);
}
__device__ __forceinline__ void mma_tf32(float* c, const uint32_t* a,
                                         const uint32_t* b) {
    asm volatile(
        "mma.sync.aligned.m16n8k8.row.col.f32.tf32.tf32.f32 "
        "{%0,%1,%2,%3}, {%4,%5,%6,%7}, {%8,%9}, {%0,%1,%2,%3};"
        : "+f"(c[0]), "+f"(c[1]), "+f"(c[2]), "+f"(c[3])
        : "r"(a[0]), "r"(a[1]), "r"(a[2]), "r"(a[3]),
          "r"(b[0]), "r"(b[1]));
}

// ---------------------------------------------------------------------------
// Weight pre-round: out[i] = tf32_rna(in[i])
// ---------------------------------------------------------------------------
__global__ __launch_bounds__(256) void roundw_kernel(
    const float* __restrict__ in, float* __restrict__ out, int n)
{
    int i = blockIdx.x * 256 + threadIdx.x;
    if (i < n) out[i] = tf32r(in[i]);
}

// ---------------------------------------------------------------------------
// tf32 mma.sync GEMM, inputs PRE-ROUNDED to tf32 (no cvt in hot loop).
// C[M,Nc] = A[M,K] @ Bw[Nc,K]^T  (+bias)(+gelu|+resid)
// CTA tile 128x128, BK=32, 2-stage cp.async double buffer.
// 128 threads = 4 warps as 2(M)x2(N); warp tile 64x64 via m16n8k8.
// mode: 0 = plain, 1 = bias+erf GELU (output tf32-rounded), 2 = bias+residual
// ---------------------------------------------------------------------------
#define ASTRIDE 36
#define STAGE_BYTES (128*ASTRIDE*4)        // 18432
#define GEMM_SMEM   (4*STAGE_BYTES)        // A0 A1 B0 B1 = 73728

__global__ __launch_bounds__(128) void gemm_tc_kernel(
    const float* __restrict__ A, const float* __restrict__ Bw,
    const float* __restrict__ bias, const float* __restrict__ resid,
    float* __restrict__ C, int M, int Nc, int K, int mode)
{
    extern __shared__ char smem[];
    uint32_t sb = smem_u32(smem);

    int tid    = threadIdx.x;
    int wid    = tid >> 5;
    int lane   = tid & 31;
    int warp_m = wid & 1;          // 0..1 -> 64-row halves
    int warp_n = wid >> 1;         // 0..1 -> 64-col halves
    int m0     = blockIdx.x * 128;
    int n0     = blockIdx.y * 128;

    const float* Ab = A  + (size_t)m0 * K;
    const float* Bb = Bw + (size_t)n0 * K;
    const int NCH = K >> 5;

    int gid = lane >> 2;           // 0..7
    int tig = lane & 3;            // 0..3

    float acc[4][8][4];
    #pragma unroll
    for (int i = 0; i < 4; i++)
        #pragma unroll
        for (int j = 0; j < 8; j++)
            #pragma unroll
            for (int q = 0; q < 4; q++) acc[i][j][q] = 0.f;

    // stage bases: A0, A1, B0, B1
    auto load_chunk = [&](int kc, int st) {
        int k0 = kc << 5;
        uint32_t as = sb + st * STAGE_BYTES;
        uint32_t bs = sb + (2 + st) * STAGE_BYTES;
        #pragma unroll
        for (int r = 0; r < 8; r++) {
            int idx = tid + r * 128;          // 0..1023
            int row = idx >> 3;
            int g   = idx & 7;
            uint32_t doff = (uint32_t)(row * (ASTRIDE*4) + g * 16);
            cp_async16(as + doff, Ab + (size_t)row * K + k0 + g * 4);
            cp_async16(bs + doff, Bb + (size_t)row * K + k0 + g * 4);
        }
        cp_commit();
    };

    load_chunk(0, 0);

    for (int i = 0; i < NCH; i++) {
        int st = i & 1;
        if (i + 1 < NCH) {
            load_chunk(i + 1, st ^ 1);
            cp_wait<1>();
        } else {
            cp_wait<0>();
        }
        __syncthreads();

        const uint32_t* Asu = (const uint32_t*)(smem + st * STAGE_BYTES);
        const uint32_t* Bsu = (const uint32_t*)(smem + (2 + st) * STAGE_BYTES);

        #pragma unroll
        for (int ks = 0; ks < 4; ks++) {
            int k0 = ks << 3;
            uint32_t afr[4][4];
            #pragma unroll
            for (int mf = 0; mf < 4; mf++) {
                int r = warp_m * 64 + mf * 16 + gid;
                afr[mf][0] = Asu[ r      * ASTRIDE + k0 + tig    ];
                afr[mf][1] = Asu[(r + 8) * ASTRIDE + k0 + tig    ];
                afr[mf][2] = Asu[ r      * ASTRIDE + k0 + tig + 4];
                afr[mf][3] = Asu[(r + 8) * ASTRIDE + k0 + tig + 4];
            }
            uint32_t bfr[8][2];
            #pragma unroll
            for (int nf = 0; nf < 8; nf++) {
                int nn = warp_n * 64 + nf * 8 + gid;
                bfr[nf][0] = Bsu[nn * ASTRIDE + k0 + tig    ];
                bfr[nf][1] = Bsu[nn * ASTRIDE + k0 + tig + 4];
            }
            #pragma unroll
            for (int mf = 0; mf < 4; mf++)
                #pragma unroll
                for (int nf = 0; nf < 8; nf++)
                    mma_tf32(acc[mf][nf], afr[mf], bfr[nf]);
        }
        __syncthreads();
    }

    // ---------------- epilogue ----------------
    #pragma unroll
    for (int mf = 0; mf < 4; mf++) {
        #pragma unroll
        for (int nf = 0; nf < 8; nf++) {
            int row = m0 + warp_m * 64 + mf * 16 + gid;
            int col = n0 + warp_n * 64 + nf * 8 + tig * 2;
            #pragma unroll
            for (int half = 0; half < 2; half++) {
                size_t rr = (size_t)(row + half * 8);
                float v0 = acc[mf][nf][half * 2 + 0];
                float v1 = acc[mf][nf][half * 2 + 1];
                if (bias) { v0 += bias[col]; v1 += bias[col + 1]; }
                if (mode == 1) {
                    v0 = 0.5f * v0 * (1.0f + erff(v0 * 0.7071067811865476f));
                    v1 = 0.5f * v1 * (1.0f + erff(v1 * 0.7071067811865476f));
                    v0 = tf32r(v0);          // h feeds fc2 GEMM
                    v1 = tf32r(v1);
                } else if (mode == 2) {
                    float2 rv = *(const float2*)&resid[rr * Nc + col];
                    v0 += rv.x; v1 += rv.y;
                }
                float2 o; o.x = v0; o.y = v1;
                *(float2*)&C[rr * Nc + col] = o;
            }
        }
    }
}

// ---------------------------------------------------------------------------
// LN1: x [B,C,H,W] -> xn [N,C] (tf32-rounded) + xpT [N,C] (exact)
// ---------------------------------------------------------------------------
__global__ __launch_bounds__(256) void ln1_kernel(
    const float* __restrict__ x, const float* __restrict__ gam,
    const float* __restrict__ bet, float* __restrict__ xn,
    float* __restrict__ xpT)
{
    const int TPB = 28;
    __shared__ float s[CCH*TPB];
    __shared__ float ps[9*TPB];
    __shared__ float pq[9*TPB];
    __shared__ float s_mean[TPB];
    __shared__ float s_rstd[TPB];

    int tid = threadIdx.x;
    int x0  = blockIdx.x * TPB;
    int y   = blockIdx.y;
    int b   = blockIdx.z;

    for (int idx = tid; idx < CCH*TPB; idx += 256) {
        int c = idx / TPB;
        int t = idx % TPB;
        s[idx] = x[(((size_t)b*CCH + c)*HH + y)*WW + x0 + t];
    }
    __syncthreads();

    if (tid < 9*TPB) {
        int sub = tid / TPB;
        int t   = tid % TPB;
        float sm = 0.f, sq = 0.f;
        for (int c = sub; c < CCH; c += 9) {
            float v = s[c*TPB + t];
            sm += v; sq += v*v;
        }
        ps[sub*TPB + t] = sm;
        pq[sub*TPB + t] = sq;
    }
    __syncthreads();
    if (tid < TPB) {
        float sm = 0.f, sq = 0.f;
        #pragma unroll
        for (int sub = 0; sub < 9; sub++) { sm += ps[sub*TPB + tid]; sq += pq[sub*TPB + tid]; }
        float mu  = sm * (1.f/CCH);
        float var = sq * (1.f/CCH) - mu*mu;
        s_mean[tid] = mu;
        s_rstd[tid] = rsqrtf(var + EPSLN);
    }
    __syncthreads();

    for (int idx = tid; idx < CCH*TPB; idx += 256) {
        int t = idx / CCH;
        int c = idx % CCH;
        float v = s[c*TPB + t];
        size_t n = (size_t)b*(HH*WW) + (size_t)y*WW + (x0 + t);
        xpT[n*CCH + c] = v;
        xn [n*CCH + c] = tf32r((v - s_mean[t]) * s_rstd[t] * gam[c] + bet[c]);
    }
}

// ---------------------------------------------------------------------------
// Multi-dilation 3x3 local attention + fused "+xn" residual (tf32-rounded out)
// ---------------------------------------------------------------------------
__global__ __launch_bounds__(384) void attn_kernel(
    const float* __restrict__ qkv, const float* __restrict__ xn,
    float* __restrict__ att)
{
    int n    = blockIdx.x;
    int b    = n / (HH*WW);
    int rem  = n % (HH*WW);
    int y    = rem / WW;
    int xx   = rem % WW;
    int w    = threadIdx.x >> 5;
    int lane = threadIdx.x & 31;

    int dil = (w >> 2) + 1;
    int c0  = w * HDIM;

    const float scale = 0.17677669529663687f;

    float q = qkv[(size_t)n*QKVC + c0 + lane];

    float logit[9];
    int   nn[9];
    #pragma unroll
    for (int e = 0; e < 9; e++) {
        int ki = e / 3, kj = e % 3;
        int ny = y  + (ki - 1) * dil;
        int nx = xx + (kj - 1) * dil;
        bool ok = ((unsigned)ny < HH) && ((unsigned)nx < WW);
        int tok = ok ? (b*(HH*WW) + ny*WW + nx) : -1;
        nn[e] = tok;
        float p = 0.f;
        if (ok) p = q * qkv[(size_t)tok*QKVC + CCH + c0 + lane];
        #pragma unroll
        for (int off = 16; off > 0; off >>= 1)
            p += __shfl_xor_sync(0xffffffffu, p, off);
        logit[e] = p * scale;
    }

    float mx = logit[0];
    #pragma unroll
    for (int e = 1; e < 9; e++) mx = fmaxf(mx, logit[e]);
    float pe[9];
    float sum = 0.f;
    #pragma unroll
    for (int e = 0; e < 9; e++) { pe[e] = __expf(logit[e] - mx); sum += pe[e]; }
    float inv = 1.f / sum;

    float o = 0.f;
    #pragma unroll
    for (int e = 0; e < 9; e++) {
        if (nn[e] >= 0)
            o = fmaf(pe[e] * inv,
                     qkv[(size_t)nn[e]*QKVC + 2*CCH + c0 + lane], o);
    }

    att[(size_t)n*CCH + c0 + lane] =
        tf32r(o + xn[(size_t)n*CCH + c0 + lane]);
}

// ---------------------------------------------------------------------------
// LN2 (output tf32-rounded: feeds fc1 GEMM)
// ---------------------------------------------------------------------------
__global__ __launch_bounds__(128) void ln2_kernel(
    const float* __restrict__ in, const float* __restrict__ gam,
    const float* __restrict__ bet, float* __restrict__ out)
{
    __shared__ float rs[4], rq[4];
    __shared__ float s_mu, s_rstd;
    int n   = blockIdx.x;
    int tid = threadIdx.x;
    const float* row = in + (size_t)n * CCH;

    float v0 = row[tid];
    float v1 = row[tid + 128];
    float v2 = row[tid + 256];
    float sm = v0 + v1 + v2;
    float sq = v0*v0 + v1*v1 + v2*v2;
    #pragma unroll
    for (int off = 16; off > 0; off >>= 1) {
        sm += __shfl_xor_sync(0xffffffffu, sm, off);
        sq += __shfl_xor_sync(0xffffffffu, sq, off);
    }
    int wid = tid >> 5, lane = tid & 31;
    if (lane == 0) { rs[wid] = sm; rq[wid] = sq; }
    __syncthreads();
    if (tid == 0) {
        float tsm = rs[0]+rs[1]+rs[2]+rs[3];
        float tsq = rq[0]+rq[1]+rq[2]+rq[3];
        float mu  = tsm * (1.f/CCH);
        float var = tsq * (1.f/CCH) - mu*mu;
        s_mu = mu;
        s_rstd = rsqrtf(var + EPSLN);
    }
    __syncthreads();
    float mu = s_mu, rstd = s_rstd;
    float* orow = out + (size_t)n * CCH;
    orow[tid      ] = tf32r((v0 - mu) * rstd * gam[tid      ] + bet[tid      ]);
    orow[tid + 128] = tf32r((v1 - mu) * rstd * gam[tid + 128] + bet[tid + 128]);
    orow[tid + 256] = tf32r((v2 - mu) * rstd * gam[tid + 256] + bet[tid + 256]);
}

// ---------------------------------------------------------------------------
// Final transpose: [B, HW, C] -> [B, C, HW]
// ---------------------------------------------------------------------------
__global__ __launch_bounds__(256) void transpose_out_kernel(
    const float* __restrict__ in, float* __restrict__ out)
{
    __shared__ float tile[32][33];
    int b  = blockIdx.z;
    int c0 = blockIdx.x * 32;
    int s0 = blockIdx.y * 32;
    int tx = threadIdx.x;
    int ty = threadIdx.y;

    #pragma unroll
    for (int rr = ty; rr < 32; rr += 8)
        tile[rr][tx] = in[((size_t)b*(HH*WW) + s0 + rr)*CCH + c0 + tx];
    __syncthreads();
    #pragma unroll
    for (int rr = ty; rr < 32; rr += 8)
        out[((size_t)b*CCH + c0 + rr)*(HH*WW) + s0 + tx] = tile[tx][rr];
}

// ---------------------------------------------------------------------------
// kernel_launch
// ---------------------------------------------------------------------------
extern "C" void kernel_launch(void* const* d_in, const int* in_sizes, int n_in,
                              void* d_out, int out_size)
{
    const float* x      = (const float*)d_in[0];
    const float* qkv_w  = (const float*)d_in[1];
    const float* proj_w = (const float*)d_in[2];
    const float* proj_b = (const float*)d_in[3];
    const float* n1_g   = (const float*)d_in[4];
    const float* n1_b   = (const float*)d_in[5];
    const float* n2_g   = (const float*)d_in[6];
    const float* n2_b   = (const float*)d_in[7];
    const float* fc1_w  = (const float*)d_in[8];
    const float* fc1_b  = (const float*)d_in[9];
    const float* fc2_w  = (const float*)d_in[10];
    const float* fc2_b  = (const float*)d_in[11];
    float* out = (float*)d_out;

    float *xn, *xpT, *qkv, *att, *xpb, *x2, *h, *xf;
    float *wq, *wp, *w1, *w2;
    cudaGetSymbolAddress((void**)&xn,  g_xn);
    cudaGetSymbolAddress((void**)&xpT, g_xpT);
    cudaGetSymbolAddress((void**)&qkv, g_qkv);
    cudaGetSymbolAddress((void**)&att, g_att);
    cudaGetSymbolAddress((void**)&xpb, g_xpb);
    cudaGetSymbolAddress((void**)&x2,  g_x2);
    cudaGetSymbolAddress((void**)&h,   g_h);
    cudaGetSymbolAddress((void**)&xf,  g_xf);
    cudaGetSymbolAddress((void**)&wq,  g_wq);
    cudaGetSymbolAddress((void**)&wp,  g_wp);
    cudaGetSymbolAddress((void**)&w1,  g_w1);
    cudaGetSymbolAddress((void**)&w2,  g_w2);

    cudaFuncSetAttribute(gemm_tc_kernel,
                         cudaFuncAttributeMaxDynamicSharedMemorySize, GEMM_SMEM);

    // 0. pre-round weights to tf32
    roundw_kernel<<<(QKVC*CCH + 255)/256, 256>>>(qkv_w,  wq, QKVC*CCH);
    roundw_kernel<<<(CCH*CCH  + 255)/256, 256>>>(proj_w, wp, CCH*CCH);
    roundw_kernel<<<(HIDN*CCH + 255)/256, 256>>>(fc1_w,  w1, HIDN*CCH);
    roundw_kernel<<<(CCH*HIDN + 255)/256, 256>>>(fc2_w,  w2, CCH*HIDN);

    // 1. LN1 + NCHW->NHWC transpose
    ln1_kernel<<<dim3(2, HH, BATCH), 256>>>(x, n1_g, n1_b, xn, xpT);

    // 2. QKV: [N,384] @ [1152,384]^T
    gemm_tc_kernel<<<dim3(NTOK/128, QKVC/128), 128, GEMM_SMEM>>>(
        xn, wq, nullptr, nullptr, qkv, NTOK, QKVC, CCH, 0);

    // 3. attention + xn residual
    attn_kernel<<<NTOK, 384>>>(qkv, xn, att);

    // 4. proj + bias + residual(x transposed)
    gemm_tc_kernel<<<dim3(NTOK/128, CCH/128), 128, GEMM_SMEM>>>(
        att, wp, proj_b, xpT, xpb, NTOK, CCH, CCH, 2);

    // 5. LN2
    ln2_kernel<<<NTOK, 128>>>(xpb, n2_g, n2_b, x2);

    // 6. fc1 + bias + exact GELU (tf32-rounded out)
    gemm_tc_kernel<<<dim3(NTOK/128, HIDN/128), 128, GEMM_SMEM>>>(
        x2, w1, fc1_b, nullptr, h, NTOK, HIDN, CCH, 1);

    // 7. fc2 + bias + residual
    gemm_tc_kernel<<<dim3(NTOK/128, CCH/128), 128, GEMM_SMEM>>>(
        h, w2, fc2_b, xpb, xf, NTOK, CCH, HIDN, 2);

    // 8. NHWC -> NCHW
    transpose_out_kernel<<<dim3(CCH/32, (HH*WW)/32, BATCH), dim3(32, 8)>>>(xf, out);
}

// round 8
// speedup vs baseline: 4.3929x; 1.6183x over previous
#include <cuda_runtime.h>
#include <cuda_fp16.h>
#include <math.h>
#include <stdint.h>

// ---------------------------------------------------------------------------
// Problem constants
// ---------------------------------------------------------------------------
#define BATCH 8
#define CCH   384
#define HH    56
#define WW    56
#define NTOK  (BATCH*HH*WW)   // 25088
#define QKVC  (3*CCH)         // 1152
#define HIDN  1536
#define NHEAD 12
#define HDIM  32
#define EPSLN 1e-5f

// ---------------------------------------------------------------------------
// Scratch
// ---------------------------------------------------------------------------
__device__ __half g_xn [(size_t)NTOK*CCH];   // LN1 out (half, feeds qkv gemm + residual)
__device__ float  g_xpT[(size_t)NTOK*CCH];   // raw transposed x (fp32 residual)
__device__ __half g_qkv[(size_t)NTOK*QKVC];  // qkv (half)
__device__ __half g_att[(size_t)NTOK*CCH];   // attn out + xn (half, feeds proj gemm)
__device__ float  g_xpb[(size_t)NTOK*CCH];   // after proj residual (fp32)
__device__ __half g_x2 [(size_t)NTOK*CCH];   // LN2 out (half)
__device__ __half g_h  [(size_t)NTOK*HIDN];  // MLP hidden (half)
__device__ float  g_xf [(size_t)NTOK*CCH];   // final token-major (fp32)
// half weights
__device__ __half g_wq[(size_t)QKVC*CCH];
__device__ __half g_wp[(size_t)CCH*CCH];
__device__ __half g_w1[(size_t)HIDN*CCH];
__device__ __half g_w2[(size_t)CCH*HIDN];

// ---------------------------------------------------------------------------
// helpers
// ---------------------------------------------------------------------------
__device__ __forceinline__ uint32_t smem_u32(const void* p) {
    uint32_t a;
    asm("{ .reg .u64 t; cvta.to.shared.u64 t, %1; cvt.u32.u64 %0, t; }"
        : "=r"(a) : "l"(p));
    return a;
}
__device__ __forceinline__ void cp_async16(uint32_t s, const void* g) {
    asm volatile("cp.async.cg.shared.global [%0], [%1], 16;"
                 :: "r"(s), "l"(g));
}
__device__ __forceinline__ void cp_commit() {
    asm volatile("cp.async.commit_group;" ::: "memory");
}
template<int N>
__device__ __forceinline__ void cp_wait() {
    asm volatile("cp.async.wait_group %0;" :: "n"(N) : "memory");
}
__device__ __forceinline__ void ldmatrix_x4(uint32_t& r0, uint32_t& r1,
                                            uint32_t& r2, uint32_t& r3,
                                            uint32_t addr) {
    asm volatile("ldmatrix.sync.aligned.m8n8.x4.shared.b16 {%0,%1,%2,%3}, [%4];"
                 : "=r"(r0), "=r"(r1), "=r"(r2), "=r"(r3) : "r"(addr));
}
__device__ __forceinline__ void mma_f16(float* c, const uint32_t* a,
                                        const uint32_t* b) {
    asm volatile(
        "mma.sync.aligned.m16n8k16.row.col.f32.f16.f16.f32 "
        "{%0,%1,%2,%3}, {%4,%5,%6,%7}, {%8,%9}, {%0,%1,%2,%3};"
        : "+f"(c[0]), "+f"(c[1]), "+f"(c[2]), "+f"(c[3])
        : "r"(a[0]), "r"(a[1]), "r"(a[2]), "r"(a[3]),
          "r"(b[0]), "r"(b[1]));
}

// ---------------------------------------------------------------------------
// Weight convert fp32 -> half
// ---------------------------------------------------------------------------
__global__ __launch_bounds__(256) void convw_kernel(
    const float* __restrict__ in, __half* __restrict__ out, int n)
{
    int i = blockIdx.x * 256 + threadIdx.x;
    if (i < n) out[i] = __float2half(in[i]);
}

// ---------------------------------------------------------------------------
// fp16 mma.sync GEMM:  C[M,Nc] = A[M,K] @ Bw[Nc,K]^T
// CTA tile 128x128, BK=64 halves (128B rows, XOR-8 swizzle), 2-stage cp.async.
// 256 threads = 8 warps as 2(M)x4(N); warp tile 64x32 via m16n8k16 + ldmatrix.
// mode: 0 = plain -> half out
//       1 = bias + exact erf GELU -> half out
//       2 = bias + fp32 residual -> float out
// ---------------------------------------------------------------------------
#define OPST  16384                 // bytes per operand tile (128 rows x 128B)
#define GEMM_SMEM (2*2*OPST)        // 2 stages x (A+B) = 65536

__global__ __launch_bounds__(256, 2) void gemm_f16_kernel(
    const __half* __restrict__ A, const __half* __restrict__ Bw,
    const float* __restrict__ bias, const float* __restrict__ resid,
    void* __restrict__ Cout, int M, int Nc, int K, int mode)
{
    extern __shared__ char smem[];
    uint32_t sb = smem_u32(smem);

    int tid    = threadIdx.x;
    int wid    = tid >> 5;
    int lane   = tid & 31;
    int warp_m = wid & 1;           // 64-row half
    int warp_n = wid >> 1;          // 32-col quarter
    int m0     = blockIdx.x * 128;
    int n0     = blockIdx.y * 128;

    const __half* Ab = A  + (size_t)m0 * K;
    const __half* Bb = Bw + (size_t)n0 * K;
    const int NCH = K >> 6;         // chunks of 64 halves

    int gid = lane >> 2;            // 0..7
    int tig = lane & 3;             // 0..3

    // ldmatrix per-thread row/sub-granule (fixed per thread)
    // A (x4): j = lane>>3:  row_off = ((lane>>3)&1)*8, k16B = (lane>>4)&1
    int arow_l = (lane & 7) + ((lane >> 3) & 1) * 8;   // within 16-row frag
    int asub   = (lane >> 4) & 1;                      // 16B sub-granule
    // B pair (x4): rows n: ((lane>>4)&1)*8 + (lane&7), k16B = (lane>>3)&1
    int brow_l = (lane & 7) + ((lane >> 4) & 1) * 8;
    int bsub   = (lane >> 3) & 1;

    float acc[4][4][4];
    #pragma unroll
    for (int i = 0; i < 4; i++)
        #pragma unroll
        for (int j = 0; j < 4; j++)
            #pragma unroll
            for (int q = 0; q < 4; q++) acc[i][j][q] = 0.f;

    // stage st: A at sb + st*2*OPST, B at +OPST
    auto load_chunk = [&](int kc, int st) {
        uint32_t abase = sb + st * (2*OPST);
        uint32_t bbase = abase + OPST;
        int kh = kc << 6;                      // k offset in halves
        #pragma unroll
        for (int r = 0; r < 8; r++) {
            int idx = tid + r * 256;           // 0..2047
            int op  = idx >> 10;               // 0=A, 1=B
            int wi  = idx & 1023;
            int row = wi >> 3;
            int g   = wi & 7;
            uint32_t dst = (op ? bbase : abase)
                         + (uint32_t)(row * 128 + ((g ^ (row & 7)) << 4));
            const __half* src = (op ? Bb : Ab) + (size_t)row * K + kh + g * 8;
            cp_async16(dst, src);
        }
        cp_commit();
    };

    load_chunk(0, 0);

    for (int i = 0; i < NCH; i++) {
        int st = i & 1;
        if (i + 1 < NCH) {
            load_chunk(i + 1, st ^ 1);
            cp_wait<1>();
        } else {
            cp_wait<0>();
        }
        __syncthreads();

        uint32_t abase = sb + st * (2*OPST);
        uint32_t bbase = abase + OPST;

        #pragma unroll
        for (int ks = 0; ks < 4; ks++) {
            uint32_t afr[4][4];
            #pragma unroll
            for (int mf = 0; mf < 4; mf++) {
                int row = warp_m * 64 + mf * 16 + arow_l;
                int gph = ((ks * 2 + asub) ^ (row & 7));
                ldmatrix_x4(afr[mf][0], afr[mf][1], afr[mf][2], afr[mf][3],
                            abase + (uint32_t)(row * 128 + gph * 16));
            }
            uint32_t bfr[4][2];
            #pragma unroll
            for (int pf = 0; pf < 2; pf++) {
                int row = warp_n * 32 + pf * 16 + brow_l;
                int gph = ((ks * 2 + bsub) ^ (row & 7));
                ldmatrix_x4(bfr[2*pf][0], bfr[2*pf][1],
                            bfr[2*pf+1][0], bfr[2*pf+1][1],
                            bbase + (uint32_t)(row * 128 + gph * 16));
            }
            #pragma unroll
            for (int mf = 0; mf < 4; mf++)
                #pragma unroll
                for (int nf = 0; nf < 4; nf++)
                    mma_f16(acc[mf][nf], afr[mf], bfr[nf]);
        }
        __syncthreads();
    }

    // ---------------- epilogue ----------------
    #pragma unroll
    for (int mf = 0; mf < 4; mf++) {
        #pragma unroll
        for (int nf = 0; nf < 4; nf++) {
            int row = m0 + warp_m * 64 + mf * 16 + gid;
            int col = n0 + warp_n * 32 + nf * 8 + tig * 2;
            #pragma unroll
            for (int half_i = 0; half_i < 2; half_i++) {
                size_t rr = (size_t)(row + half_i * 8);
                float v0 = acc[mf][nf][half_i * 2 + 0];
                float v1 = acc[mf][nf][half_i * 2 + 1];
                if (bias) { v0 += bias[col]; v1 += bias[col + 1]; }
                if (mode == 1) {
                    v0 = 0.5f * v0 * (1.0f + erff(v0 * 0.7071067811865476f));
                    v1 = 0.5f * v1 * (1.0f + erff(v1 * 0.7071067811865476f));
                }
                if (mode == 2) {
                    float2 rv = *(const float2*)&resid[rr * Nc + col];
                    v0 += rv.x; v1 += rv.y;
                    float2 o; o.x = v0; o.y = v1;
                    *(float2*)&((float*)Cout)[rr * Nc + col] = o;
                } else {
                    __half2 o = __floats2half2_rn(v0, v1);
                    *(__half2*)&((__half*)Cout)[rr * Nc + col] = o;
                }
            }
        }
    }
}

// ---------------------------------------------------------------------------
// LN1: x [B,C,H,W] -> xn [N,C] (half) + xpT [N,C] (fp32)
// ---------------------------------------------------------------------------
__global__ __launch_bounds__(256) void ln1_kernel(
    const float* __restrict__ x, const float* __restrict__ gam,
    const float* __restrict__ bet, __half* __restrict__ xn,
    float* __restrict__ xpT)
{
    const int TPB = 28;
    __shared__ float s[CCH*TPB];
    __shared__ float ps[9*TPB];
    __shared__ float pq[9*TPB];
    __shared__ float s_mean[TPB];
    __shared__ float s_rstd[TPB];

    int tid = threadIdx.x;
    int x0  = blockIdx.x * TPB;
    int y   = blockIdx.y;
    int b   = blockIdx.z;

    for (int idx = tid; idx < CCH*TPB; idx += 256) {
        int c = idx / TPB;
        int t = idx % TPB;
        s[idx] = x[(((size_t)b*CCH + c)*HH + y)*WW + x0 + t];
    }
    __syncthreads();

    if (tid < 9*TPB) {
        int sub = tid / TPB;
        int t   = tid % TPB;
        float sm = 0.f, sq = 0.f;
        for (int c = sub; c < CCH; c += 9) {
            float v = s[c*TPB + t];
            sm += v; sq += v*v;
        }
        ps[sub*TPB + t] = sm;
        pq[sub*TPB + t] = sq;
    }
    __syncthreads();
    if (tid < TPB) {
        float sm = 0.f, sq = 0.f;
        #pragma unroll
        for (int sub = 0; sub < 9; sub++) { sm += ps[sub*TPB + tid]; sq += pq[sub*TPB + tid]; }
        float mu  = sm * (1.f/CCH);
        float var = sq * (1.f/CCH) - mu*mu;
        s_mean[tid] = mu;
        s_rstd[tid] = rsqrtf(var + EPSLN);
    }
    __syncthreads();

    for (int idx = tid; idx < CCH*TPB; idx += 256) {
        int t = idx / CCH;
        int c = idx % CCH;
        float v = s[c*TPB + t];
        size_t n = (size_t)b*(HH*WW) + (size_t)y*WW + (x0 + t);
        xpT[n*CCH + c] = v;
        xn [n*CCH + c] =
            __float2half((v - s_mean[t]) * s_rstd[t] * gam[c] + bet[c]);
    }
}

// ---------------------------------------------------------------------------
// Multi-dilation 3x3 local attention + fused "+xn" residual (half in/out)
// ---------------------------------------------------------------------------
__global__ __launch_bounds__(384) void attn_kernel(
    const __half* __restrict__ qkv, const __half* __restrict__ xn,
    __half* __restrict__ att)
{
    int n    = blockIdx.x;
    int b    = n / (HH*WW);
    int rem  = n % (HH*WW);
    int y    = rem / WW;
    int xx   = rem % WW;
    int w    = threadIdx.x >> 5;
    int lane = threadIdx.x & 31;

    int dil = (w >> 2) + 1;
    int c0  = w * HDIM;

    const float scale = 0.17677669529663687f;

    float q = __half2float(qkv[(size_t)n*QKVC + c0 + lane]);

    float logit[9];
    int   nn[9];
    #pragma unroll
    for (int e = 0; e < 9; e++) {
        int ki = e / 3, kj = e % 3;
        int ny = y  + (ki - 1) * dil;
        int nx = xx + (kj - 1) * dil;
        bool ok = ((unsigned)ny < HH) && ((unsigned)nx < WW);
        int tok = ok ? (b*(HH*WW) + ny*WW + nx) : -1;
        nn[e] = tok;
        float p = 0.f;
        if (ok) p = q * __half2float(qkv[(size_t)tok*QKVC + CCH + c0 + lane]);
        #pragma unroll
        for (int off = 16; off > 0; off >>= 1)
            p += __shfl_xor_sync(0xffffffffu, p, off);
        logit[e] = p * scale;
    }

    float mx = logit[0];
    #pragma unroll
    for (int e = 1; e < 9; e++) mx = fmaxf(mx, logit[e]);
    float pe[9];
    float sum = 0.f;
    #pragma unroll
    for (int e = 0; e < 9; e++) { pe[e] = __expf(logit[e] - mx); sum += pe[e]; }
    float inv = 1.f / sum;

    float o = 0.f;
    #pragma unroll
    for (int e = 0; e < 9; e++) {
        if (nn[e] >= 0)
            o = fmaf(pe[e] * inv,
                     __half2float(qkv[(size_t)nn[e]*QKVC + 2*CCH + c0 + lane]), o);
    }

    att[(size_t)n*CCH + c0 + lane] =
        __float2half(o + __half2float(xn[(size_t)n*CCH + c0 + lane]));
}

// ---------------------------------------------------------------------------
// LN2: fp32 in -> half out
// ---------------------------------------------------------------------------
__global__ __launch_bounds__(128) void ln2_kernel(
    const float* __restrict__ in, const float* __restrict__ gam,
    const float* __restrict__ bet, __half* __restrict__ out)
{
    __shared__ float rs[4], rq[4];
    __shared__ float s_mu, s_rstd;
    int n   = blockIdx.x;
    int tid = threadIdx.x;
    const float* row = in + (size_t)n * CCH;

    float v0 = row[tid];
    float v1 = row[tid + 128];
    float v2 = row[tid + 256];
    float sm = v0 + v1 + v2;
    float sq = v0*v0 + v1*v1 + v2*v2;
    #pragma unroll
    for (int off = 16; off > 0; off >>= 1) {
        sm += __shfl_xor_sync(0xffffffffu, sm, off);
        sq += __shfl_xor_sync(0xffffffffu, sq, off);
    }
    int wid = tid >> 5, lane = tid & 31;
    if (lane == 0) { rs[wid] = sm; rq[wid] = sq; }
    __syncthreads();
    if (tid == 0) {
        float tsm = rs[0]+rs[1]+rs[2]+rs[3];
        float tsq = rq[0]+rq[1]+rq[2]+rq[3];
        float mu  = tsm * (1.f/CCH);
        float var = tsq * (1.f/CCH) - mu*mu;
        s_mu = mu;
        s_rstd = rsqrtf(var + EPSLN);
    }
    __syncthreads();
    float mu = s_mu, rstd = s_rstd;
    __half* orow = out + (size_t)n * CCH;
    orow[tid      ] = __float2half((v0 - mu) * rstd * gam[tid      ] + bet[tid      ]);
    orow[tid + 128] = __float2half((v1 - mu) * rstd * gam[tid + 128] + bet[tid + 128]);
    orow[tid + 256] = __float2half((v2 - mu) * rstd * gam[tid + 256] + bet[tid + 256]);
}

// ---------------------------------------------------------------------------
// Final transpose: [B, HW, C] -> [B, C, HW]
// ---------------------------------------------------------------------------
__global__ __launch_bounds__(256) void transpose_out_kernel(
    const float* __restrict__ in, float* __restrict__ out)
{
    __shared__ float tile[32][33];
    int b  = blockIdx.z;
    int c0 = blockIdx.x * 32;
    int s0 = blockIdx.y * 32;
    int tx = threadIdx.x;
    int ty = threadIdx.y;

    #pragma unroll
    for (int rr = ty; rr < 32; rr += 8)
        tile[rr][tx] = in[((size_t)b*(HH*WW) + s0 + rr)*CCH + c0 + tx];
    __syncthreads();
    #pragma unroll
    for (int rr = ty; rr < 32; rr += 8)
        out[((size_t)b*CCH + c0 + rr)*(HH*WW) + s0 + tx] = tile[tx][rr];
}

// ---------------------------------------------------------------------------
// kernel_launch
// ---------------------------------------------------------------------------
extern "C" void kernel_launch(void* const* d_in, const int* in_sizes, int n_in,
                              void* d_out, int out_size)
{
    const float* x      = (const float*)d_in[0];
    const float* qkv_w  = (const float*)d_in[1];
    const float* proj_w = (const float*)d_in[2];
    const float* proj_b = (const float*)d_in[3];
    const float* n1_g   = (const float*)d_in[4];
    const float* n1_b   = (const float*)d_in[5];
    const float* n2_g   = (const float*)d_in[6];
    const float* n2_b   = (const float*)d_in[7];
    const float* fc1_w  = (const float*)d_in[8];
    const float* fc1_b  = (const float*)d_in[9];
    const float* fc2_w  = (const float*)d_in[10];
    const float* fc2_b  = (const float*)d_in[11];
    float* out = (float*)d_out;

    __half *xn, *qkv, *att, *x2, *h, *wq, *wp, *w1, *w2;
    float *xpT, *xpb, *xf;
    cudaGetSymbolAddress((void**)&xn,  g_xn);
    cudaGetSymbolAddress((void**)&xpT, g_xpT);
    cudaGetSymbolAddress((void**)&qkv, g_qkv);
    cudaGetSymbolAddress((void**)&att, g_att);
    cudaGetSymbolAddress((void**)&xpb, g_xpb);
    cudaGetSymbolAddress((void**)&x2,  g_x2);
    cudaGetSymbolAddress((void**)&h,   g_h);
    cudaGetSymbolAddress((void**)&xf,  g_xf);
    cudaGetSymbolAddress((void**)&wq,  g_wq);
    cudaGetSymbolAddress((void**)&wp,  g_wp);
    cudaGetSymbolAddress((void**)&w1,  g_w1);
    cudaGetSymbolAddress((void**)&w2,  g_w2);

    cudaFuncSetAttribute(gemm_f16_kernel,
                         cudaFuncAttributeMaxDynamicSharedMemorySize, GEMM_SMEM);

    // 0. convert weights to half
    convw_kernel<<<(QKVC*CCH + 255)/256, 256>>>(qkv_w,  wq, QKVC*CCH);
    convw_kernel<<<(CCH*CCH  + 255)/256, 256>>>(proj_w, wp, CCH*CCH);
    convw_kernel<<<(HIDN*CCH + 255)/256, 256>>>(fc1_w,  w1, HIDN*CCH);
    convw_kernel<<<(CCH*HIDN + 255)/256, 256>>>(fc2_w,  w2, CCH*HIDN);

    // 1. LN1 + NCHW->NHWC transpose
    ln1_kernel<<<dim3(2, HH, BATCH), 256>>>(x, n1_g, n1_b, xn, xpT);

    // 2. QKV: [N,384] @ [1152,384]^T -> half
    gemm_f16_kernel<<<dim3(NTOK/128, QKVC/128), 256, GEMM_SMEM>>>(
        xn, wq, nullptr, nullptr, qkv, NTOK, QKVC, CCH, 0);

    // 3. attention + xn residual -> half
    attn_kernel<<<NTOK, 384>>>(qkv, xn, att);

    // 4. proj + bias + residual(xpT) -> fp32
    gemm_f16_kernel<<<dim3(NTOK/128, CCH/128), 256, GEMM_SMEM>>>(
        att, wp, proj_b, xpT, xpb, NTOK, CCH, CCH, 2);

    // 5. LN2 -> half
    ln2_kernel<<<NTOK, 128>>>(xpb, n2_g, n2_b, x2);

    // 6. fc1 + bias + exact GELU -> half
    gemm_f16_kernel<<<dim3(NTOK/128, HIDN/128), 256, GEMM_SMEM>>>(
        x2, w1, fc1_b, nullptr, h, NTOK, HIDN, CCH, 1);

    // 7. fc2 + bias + residual(xpb) -> fp32
    gemm_f16_kernel<<<dim3(NTOK/128, CCH/128), 256, GEMM_SMEM>>>(
        h, w2, fc2_b, xpb, xf, NTOK, CCH, HIDN, 2);

    // 8. NHWC -> NCHW
    transpose_out_kernel<<<dim3(CCH/32, (HH*WW)/32, BATCH), dim3(32, 8)>>>(xf, out);
}

// round 9
// speedup vs baseline: 4.4690x; 1.0173x over previous
#include <cuda_runtime.h>
#include <cuda_fp16.h>
#include <math.h>
#include <stdint.h>

// ---------------------------------------------------------------------------
// Problem constants
// ---------------------------------------------------------------------------
#define BATCH 8
#define CCH   384
#define HH    56
#define WW    56
#define HWSZ  (HH*WW)         // 3136
#define NTOK  (BATCH*HWSZ)    // 25088
#define QKVC  (3*CCH)         // 1152
#define HIDN  1536
#define NHEAD 12
#define HDIM  32
#define EPSLN 1e-5f

// ---------------------------------------------------------------------------
// Scratch
// ---------------------------------------------------------------------------
__device__ __half g_xn [(size_t)NTOK*CCH];
__device__ float  g_xpT[(size_t)NTOK*CCH];
__device__ __half g_qkv[(size_t)NTOK*QKVC];
__device__ __half g_att[(size_t)NTOK*CCH];
__device__ float  g_xpb[(size_t)NTOK*CCH];
__device__ __half g_x2 [(size_t)NTOK*CCH];
__device__ __half g_h  [(size_t)NTOK*HIDN];
__device__ __half g_wq[(size_t)QKVC*CCH];
__device__ __half g_wp[(size_t)CCH*CCH];
__device__ __half g_w1[(size_t)HIDN*CCH];
__device__ __half g_w2[(size_t)CCH*HIDN];

// ---------------------------------------------------------------------------
// helpers
// ---------------------------------------------------------------------------
__device__ __forceinline__ uint32_t smem_u32(const void* p) {
    uint32_t a;
    asm("{ .reg .u64 t; cvta.to.shared.u64 t, %1; cvt.u32.u64 %0, t; }"
        : "=r"(a) : "l"(p));
    return a;
}
__device__ __forceinline__ void cp_async16(uint32_t s, const void* g) {
    asm volatile("cp.async.cg.shared.global [%0], [%1], 16;"
                 :: "r"(s), "l"(g));
}
__device__ __forceinline__ void cp_commit() {
    asm volatile("cp.async.commit_group;" ::: "memory");
}
template<int N>
__device__ __forceinline__ void cp_wait() {
    asm volatile("cp.async.wait_group %0;" :: "n"(N) : "memory");
}
__device__ __forceinline__ void ldmatrix_x4(uint32_t& r0, uint32_t& r1,
                                            uint32_t& r2, uint32_t& r3,
                                            uint32_t addr) {
    asm volatile("ldmatrix.sync.aligned.m8n8.x4.shared.b16 {%0,%1,%2,%3}, [%4];"
                 : "=r"(r0), "=r"(r1), "=r"(r2), "=r"(r3) : "r"(addr));
}
__device__ __forceinline__ void mma_f16(float* c, const uint32_t* a,
                                        const uint32_t* b) {
    asm volatile(
        "mma.sync.aligned.m16n8k16.row.col.f32.f16.f16.f32 "
        "{%0,%1,%2,%3}, {%4,%5,%6,%7}, {%8,%9}, {%0,%1,%2,%3};"
        : "+f"(c[0]), "+f"(c[1]), "+f"(c[2]), "+f"(c[3])
        : "r"(a[0]), "r"(a[1]), "r"(a[2]), "r"(a[3]),
          "r"(b[0]), "r"(b[1]));
}

// ---------------------------------------------------------------------------
// Fused weight convert fp32 -> half (all 4 weights in one launch)
// ---------------------------------------------------------------------------
#define WN1 (QKVC*CCH)
#define WN2 (CCH*CCH)
#define WN3 (HIDN*CCH)
#define WN4 (CCH*HIDN)
#define WNT (WN1+WN2+WN3+WN4)

__global__ __launch_bounds__(256) void convw4_kernel(
    const float* __restrict__ s1, const float* __restrict__ s2,
    const float* __restrict__ s3, const float* __restrict__ s4,
    __half* __restrict__ d1, __half* __restrict__ d2,
    __half* __restrict__ d3, __half* __restrict__ d4)
{
    int i = blockIdx.x * 256 + threadIdx.x;
    if (i < WN1) { d1[i] = __float2half(s1[i]); return; }
    i -= WN1;
    if (i < WN2) { d2[i] = __float2half(s2[i]); return; }
    i -= WN2;
    if (i < WN3) { d3[i] = __float2half(s3[i]); return; }
    i -= WN3;
    if (i < WN4) d4[i] = __float2half(s4[i]);
}

// ---------------------------------------------------------------------------
// fp16 mma.sync GEMM:  C[M,Nc] = A[M,K] @ Bw[Nc,K]^T
// CTA tile 128x128, BK=64 halves (128B rows, XOR swizzle), 3-stage cp.async.
// 256 threads = 8 warps as 2(M)x4(N); warp tile 64x32 via m16n8k16 + ldmatrix.
// mode: 0 = plain -> half out
//       1 = bias + exact erf GELU -> half out
//       2 = bias + fp32 residual -> float out [N,C]
//       3 = bias + fp32 residual -> float out [B,C,HW] (fused transpose)
// ---------------------------------------------------------------------------
#define OPST   16384                 // bytes per operand tile (128 x 128B)
#define NSTAGE 3
#define GEMM_SMEM (NSTAGE*2*OPST)    // 98304

__global__ __launch_bounds__(256, 2) void gemm_f16_kernel(
    const __half* __restrict__ A, const __half* __restrict__ Bw,
    const float* __restrict__ bias, const float* __restrict__ resid,
    void* __restrict__ Cout, int M, int Nc, int K, int mode)
{
    extern __shared__ char smem[];
    uint32_t sb = smem_u32(smem);

    int tid    = threadIdx.x;
    int wid    = tid >> 5;
    int lane   = tid & 31;
    int warp_m = wid & 1;
    int warp_n = wid >> 1;
    int m0     = blockIdx.x * 128;
    int n0     = blockIdx.y * 128;

    const __half* Ab = A  + (size_t)m0 * K;
    const __half* Bb = Bw + (size_t)n0 * K;
    const int NCH = K >> 6;

    int gid = lane >> 2;
    int tig = lane & 3;

    int arow_l = (lane & 7) + ((lane >> 3) & 1) * 8;
    int asub   = (lane >> 4) & 1;
    int brow_l = (lane & 7) + ((lane >> 4) & 1) * 8;
    int bsub   = (lane >> 3) & 1;

    float acc[4][4][4];
    #pragma unroll
    for (int i = 0; i < 4; i++)
        #pragma unroll
        for (int j = 0; j < 4; j++)
            #pragma unroll
            for (int q = 0; q < 4; q++) acc[i][j][q] = 0.f;

    auto load_chunk = [&](int kc, int st) {
        uint32_t abase = sb + st * (2*OPST);
        uint32_t bbase = abase + OPST;
        int kh = kc << 6;
        #pragma unroll
        for (int r = 0; r < 8; r++) {
            int idx = tid + r * 256;
            int op  = idx >> 10;
            int wi  = idx & 1023;
            int row = wi >> 3;
            int g   = wi & 7;
            uint32_t dst = (op ? bbase : abase)
                         + (uint32_t)(row * 128 + ((g ^ (row & 7)) << 4));
            const __half* src = (op ? Bb : Ab) + (size_t)row * K + kh + g * 8;
            cp_async16(dst, src);
        }
        cp_commit();
    };

    load_chunk(0, 0);
    load_chunk(1, 1);

    for (int i = 0; i < NCH; i++) {
        if (i < NCH - 1) cp_wait<1>(); else cp_wait<0>();
        __syncthreads();

        int st = i % NSTAGE;
        uint32_t abase = sb + st * (2*OPST);
        uint32_t bbase = abase + OPST;

        #pragma unroll
        for (int ks = 0; ks < 4; ks++) {
            uint32_t afr[4][4];
            #pragma unroll
            for (int mf = 0; mf < 4; mf++) {
                int row = warp_m * 64 + mf * 16 + arow_l;
                int gph = ((ks * 2 + asub) ^ (row & 7));
                ldmatrix_x4(afr[mf][0], afr[mf][1], afr[mf][2], afr[mf][3],
                            abase + (uint32_t)(row * 128 + gph * 16));
            }
            uint32_t bfr[4][2];
            #pragma unroll
            for (int pf = 0; pf < 2; pf++) {
                int row = warp_n * 32 + pf * 16 + brow_l;
                int gph = ((ks * 2 + bsub) ^ (row & 7));
                ldmatrix_x4(bfr[2*pf][0], bfr[2*pf][1],
                            bfr[2*pf+1][0], bfr[2*pf+1][1],
                            bbase + (uint32_t)(row * 128 + gph * 16));
            }
            #pragma unroll
            for (int mf = 0; mf < 4; mf++)
                #pragma unroll
                for (int nf = 0; nf < 4; nf++)
                    mma_f16(acc[mf][nf], afr[mf], bfr[nf]);
        }

        if (i + 2 < NCH) load_chunk(i + 2, (i + 2) % NSTAGE);
    }

    // ---------------- epilogue ----------------
    if (mode == 3) {
        // bias + residual, then stage to smem and write transposed [B,C,HW]
        __syncthreads();                       // mainloop fully done, reuse smem
        float* tile = (float*)smem;            // [128][129]
        #pragma unroll
        for (int mf = 0; mf < 4; mf++) {
            #pragma unroll
            for (int nf = 0; nf < 4; nf++) {
                int rl = warp_m * 64 + mf * 16 + gid;
                int cl = warp_n * 32 + nf * 8 + tig * 2;
                #pragma unroll
                for (int half_i = 0; half_i < 2; half_i++) {
                    int r = rl + half_i * 8;
                    size_t rr = (size_t)(m0 + r);
                    float v0 = acc[mf][nf][half_i * 2 + 0] + bias[n0 + cl];
                    float v1 = acc[mf][nf][half_i * 2 + 1] + bias[n0 + cl + 1];
                    float2 rv = *(const float2*)&resid[rr * Nc + n0 + cl];
                    v0 += rv.x; v1 += rv.y;
                    tile[r * 129 + cl    ] = v0;
                    tile[r * 129 + cl + 1] = v1;
                }
            }
        }
        __syncthreads();
        float* out = (float*)Cout;
        #pragma unroll
        for (int cs = 0; cs < 16; cs++) {
            int c = wid * 16 + cs;
            #pragma unroll
            for (int rs = 0; rs < 4; rs++) {
                int r  = rs * 32 + lane;
                int rr = m0 + r;
                int b  = rr / HWSZ;
                int s  = rr - b * HWSZ;
                out[((size_t)b * CCH + n0 + c) * HWSZ + s] = tile[r * 129 + c];
            }
        }
        return;
    }

    #pragma unroll
    for (int mf = 0; mf < 4; mf++) {
        #pragma unroll
        for (int nf = 0; nf < 4; nf++) {
            int row = m0 + warp_m * 64 + mf * 16 + gid;
            int col = n0 + warp_n * 32 + nf * 8 + tig * 2;
            #pragma unroll
            for (int half_i = 0; half_i < 2; half_i++) {
                size_t rr = (size_t)(row + half_i * 8);
                float v0 = acc[mf][nf][half_i * 2 + 0];
                float v1 = acc[mf][nf][half_i * 2 + 1];
                if (bias) { v0 += bias[col]; v1 += bias[col + 1]; }
                if (mode == 1) {
                    v0 = 0.5f * v0 * (1.0f + erff(v0 * 0.7071067811865476f));
                    v1 = 0.5f * v1 * (1.0f + erff(v1 * 0.7071067811865476f));
                }
                if (mode == 2) {
                    float2 rv = *(const float2*)&resid[rr * Nc + col];
                    v0 += rv.x; v1 += rv.y;
                    float2 o; o.x = v0; o.y = v1;
                    *(float2*)&((float*)Cout)[rr * Nc + col] = o;
                } else {
                    __half2 o = __floats2half2_rn(v0, v1);
                    *(__half2*)&((__half*)Cout)[rr * Nc + col] = o;
                }
            }
        }
    }
}

// ---------------------------------------------------------------------------
// LN1: x [B,C,H,W] -> xn [N,C] (half) + xpT [N,C] (fp32)
// ---------------------------------------------------------------------------
__global__ __launch_bounds__(256) void ln1_kernel(
    const float* __restrict__ x, const float* __restrict__ gam,
    const float* __restrict__ bet, __half* __restrict__ xn,
    float* __restrict__ xpT)
{
    const int TPB = 28;
    __shared__ float s[CCH*TPB];
    __shared__ float ps[9*TPB];
    __shared__ float pq[9*TPB];
    __shared__ float s_mean[TPB];
    __shared__ float s_rstd[TPB];

    int tid = threadIdx.x;
    int x0  = blockIdx.x * TPB;
    int y   = blockIdx.y;
    int b   = blockIdx.z;

    for (int idx = tid; idx < CCH*TPB; idx += 256) {
        int c = idx / TPB;
        int t = idx % TPB;
        s[idx] = x[(((size_t)b*CCH + c)*HH + y)*WW + x0 + t];
    }
    __syncthreads();

    if (tid < 9*TPB) {
        int sub = tid / TPB;
        int t   = tid % TPB;
        float sm = 0.f, sq = 0.f;
        for (int c = sub; c < CCH; c += 9) {
            float v = s[c*TPB + t];
            sm += v; sq += v*v;
        }
        ps[sub*TPB + t] = sm;
        pq[sub*TPB + t] = sq;
    }
    __syncthreads();
    if (tid < TPB) {
        float sm = 0.f, sq = 0.f;
        #pragma unroll
        for (int sub = 0; sub < 9; sub++) { sm += ps[sub*TPB + tid]; sq += pq[sub*TPB + tid]; }
        float mu  = sm * (1.f/CCH);
        float var = sq * (1.f/CCH) - mu*mu;
        s_mean[tid] = mu;
        s_rstd[tid] = rsqrtf(var + EPSLN);
    }
    __syncthreads();

    for (int idx = tid; idx < CCH*TPB; idx += 256) {
        int t = idx / CCH;
        int c = idx % CCH;
        float v = s[c*TPB + t];
        size_t n = (size_t)b*HWSZ + (size_t)y*WW + (x0 + t);
        xpT[n*CCH + c] = v;
        xn [n*CCH + c] =
            __float2half((v - s_mean[t]) * s_rstd[t] * gam[c] + bet[c]);
    }
}

// ---------------------------------------------------------------------------
// Multi-dilation 3x3 local attention + fused "+xn" residual (half in/out)
// ---------------------------------------------------------------------------
__global__ __launch_bounds__(384) void attn_kernel(
    const __half* __restrict__ qkv, const __half* __restrict__ xn,
    __half* __restrict__ att)
{
    int n    = blockIdx.x;
    int b    = n / HWSZ;
    int rem  = n % HWSZ;
    int y    = rem / WW;
    int xx   = rem % WW;
    int w    = threadIdx.x >> 5;
    int lane = threadIdx.x & 31;

    int dil = (w >> 2) + 1;
    int c0  = w * HDIM;

    const float scale = 0.17677669529663687f;

    float q = __half2float(qkv[(size_t)n*QKVC + c0 + lane]);

    float logit[9];
    int   nn[9];
    #pragma unroll
    for (int e = 0; e < 9; e++) {
        int ki = e / 3, kj = e % 3;
        int ny = y  + (ki - 1) * dil;
        int nx = xx + (kj - 1) * dil;
        bool ok = ((unsigned)ny < HH) && ((unsigned)nx < WW);
        int tok = ok ? (b*HWSZ + ny*WW + nx) : -1;
        nn[e] = tok;
        float p = 0.f;
        if (ok) p = q * __half2float(qkv[(size_t)tok*QKVC + CCH + c0 + lane]);
        #pragma unroll
        for (int off = 16; off > 0; off >>= 1)
            p += __shfl_xor_sync(0xffffffffu, p, off);
        logit[e] = p * scale;
    }

    float mx = logit[0];
    #pragma unroll
    for (int e = 1; e < 9; e++) mx = fmaxf(mx, logit[e]);
    float pe[9];
    float sum = 0.f;
    #pragma unroll
    for (int e = 0; e < 9; e++) { pe[e] = __expf(logit[e] - mx); sum += pe[e]; }
    float inv = 1.f / sum;

    float o = 0.f;
    #pragma unroll
    for (int e = 0; e < 9; e++) {
        if (nn[e] >= 0)
            o = fmaf(pe[e] * inv,
                     __half2float(qkv[(size_t)nn[e]*QKVC + 2*CCH + c0 + lane]), o);
    }

    att[(size_t)n*CCH + c0 + lane] =
        __float2half(o + __half2float(xn[(size_t)n*CCH + c0 + lane]));
}

// ---------------------------------------------------------------------------
// LN2: fp32 in -> half out
// ---------------------------------------------------------------------------
__global__ __launch_bounds__(128) void ln2_kernel(
    const float* __restrict__ in, const float* __restrict__ gam,
    const float* __restrict__ bet, __half* __restrict__ out)
{
    __shared__ float rs[4], rq[4];
    __shared__ float s_mu, s_rstd;
    int n   = blockIdx.x;
    int tid = threadIdx.x;
    const float* row = in + (size_t)n * CCH;

    float v0 = row[tid];
    float v1 = row[tid + 128];
    float v2 = row[tid + 256];
    float sm = v0 + v1 + v2;
    float sq = v0*v0 + v1*v1 + v2*v2;
    #pragma unroll
    for (int off = 16; off > 0; off >>= 1) {
        sm += __shfl_xor_sync(0xffffffffu, sm, off);
        sq += __shfl_xor_sync(0xffffffffu, sq, off);
    }
    int wid = tid >> 5, lane = tid & 31;
    if (lane == 0) { rs[wid] = sm; rq[wid] = sq; }
    __syncthreads();
    if (tid == 0) {
        float tsm = rs[0]+rs[1]+rs[2]+rs[3];
        float tsq = rq[0]+rq[1]+rq[2]+rq[3];
        float mu  = tsm * (1.f/CCH);
        float var = tsq * (1.f/CCH) - mu*mu;
        s_mu = mu;
        s_rstd = rsqrtf(var + EPSLN);
    }
    __syncthreads();
    float mu = s_mu, rstd = s_rstd;
    __half* orow = out + (size_t)n * CCH;
    orow[tid      ] = __float2half((v0 - mu) * rstd * gam[tid      ] + bet[tid      ]);
    orow[tid + 128] = __float2half((v1 - mu) * rstd * gam[tid + 128] + bet[tid + 128]);
    orow[tid + 256] = __float2half((v2 - mu) * rstd * gam[tid + 256] + bet[tid + 256]);
}

// ---------------------------------------------------------------------------
// kernel_launch
// ---------------------------------------------------------------------------
extern "C" void kernel_launch(void* const* d_in, const int* in_sizes, int n_in,
                              void* d_out, int out_size)
{
    const float* x      = (const float*)d_in[0];
    const float* qkv_w  = (const float*)d_in[1];
    const float* proj_w = (const float*)d_in[2];
    const float* proj_b = (const float*)d_in[3];
    const float* n1_g   = (const float*)d_in[4];
    const float* n1_b   = (const float*)d_in[5];
    const float* n2_g   = (const float*)d_in[6];
    const float* n2_b   = (const float*)d_in[7];
    const float* fc1_w  = (const float*)d_in[8];
    const float* fc1_b  = (const float*)d_in[9];
    const float* fc2_w  = (const float*)d_in[10];
    const float* fc2_b  = (const float*)d_in[11];
    float* out = (float*)d_out;

    __half *xn, *qkv, *att, *x2, *h, *wq, *wp, *w1, *w2;
    float *xpT, *xpb;
    cudaGetSymbolAddress((void**)&xn,  g_xn);
    cudaGetSymbolAddress((void**)&xpT, g_xpT);
    cudaGetSymbolAddress((void**)&qkv, g_qkv);
    cudaGetSymbolAddress((void**)&att, g_att);
    cudaGetSymbolAddress((void**)&xpb, g_xpb);
    cudaGetSymbolAddress((void**)&x2,  g_x2);
    cudaGetSymbolAddress((void**)&h,   g_h);
    cudaGetSymbolAddress((void**)&wq,  g_wq);
    cudaGetSymbolAddress((void**)&wp,  g_wp);
    cudaGetSymbolAddress((void**)&w1,  g_w1);
    cudaGetSymbolAddress((void**)&w2,  g_w2);

    cudaFuncSetAttribute(gemm_f16_kernel,
                         cudaFuncAttributeMaxDynamicSharedMemorySize, GEMM_SMEM);

    // 0. convert all weights to half (single launch)
    convw4_kernel<<<(WNT + 255)/256, 256>>>(qkv_w, proj_w, fc1_w, fc2_w,
                                            wq, wp, w1, w2);

    // 1. LN1 + NCHW->NHWC transpose
    ln1_kernel<<<dim3(2, HH, BATCH), 256>>>(x, n1_g, n1_b, xn, xpT);

    // 2. QKV: [N,384] @ [1152,384]^T -> half
    gemm_f16_kernel<<<dim3(NTOK/128, QKVC/128), 256, GEMM_SMEM>>>(
        xn, wq, nullptr, nullptr, qkv, NTOK, QKVC, CCH, 0);

    // 3. attention + xn residual -> half
    attn_kernel<<<NTOK, 384>>>(qkv, xn, att);

    // 4. proj + bias + residual(xpT) -> fp32 [N,C]
    gemm_f16_kernel<<<dim3(NTOK/128, CCH/128), 256, GEMM_SMEM>>>(
        att, wp, proj_b, xpT, xpb, NTOK, CCH, CCH, 2);

    // 5. LN2 -> half
    ln2_kernel<<<NTOK, 128>>>(xpb, n2_g, n2_b, x2);

    // 6. fc1 + bias + exact GELU -> half
    gemm_f16_kernel<<<dim3(NTOK/128, HIDN/128), 256, GEMM_SMEM>>>(
        x2, w1, fc1_b, nullptr, h, NTOK, HIDN, CCH, 1);

    // 7. fc2 + bias + residual(xpb) -> fp32 [B,C,HW] (fused transpose)
    gemm_f16_kernel<<<dim3(NTOK/128, CCH/128), 256, GEMM_SMEM>>>(
        h, w2, fc2_b, xpb, out, NTOK, CCH, HIDN, 3);
}

// round 10
// speedup vs baseline: 5.2105x; 1.1659x over previous
#include <cuda_runtime.h>
#include <cuda_fp16.h>
#include <math.h>
#include <stdint.h>

// ---------------------------------------------------------------------------
// Problem constants
// ---------------------------------------------------------------------------
#define BATCH 8
#define CCH   384
#define HH    56
#define WW    56
#define HWSZ  (HH*WW)         // 3136
#define NTOK  (BATCH*HWSZ)    // 25088
#define QKVC  (3*CCH)         // 1152
#define HIDN  1536
#define NHEAD 12
#define HDIM  32
#define EPSLN 1e-5f

// ---------------------------------------------------------------------------
// Scratch
// ---------------------------------------------------------------------------
__device__ __half g_xn [(size_t)NTOK*CCH];
__device__ float  g_xpT[(size_t)NTOK*CCH];
__device__ __half g_qkv[(size_t)NTOK*QKVC];
__device__ __half g_att[(size_t)NTOK*CCH];
__device__ float  g_xpb[(size_t)NTOK*CCH];
__device__ __half g_x2 [(size_t)NTOK*CCH];
__device__ __half g_h  [(size_t)NTOK*HIDN];
__device__ __half g_wq[(size_t)QKVC*CCH];
__device__ __half g_wp[(size_t)CCH*CCH];
__device__ __half g_w1[(size_t)HIDN*CCH];
__device__ __half g_w2[(size_t)CCH*HIDN];

// ---------------------------------------------------------------------------
// helpers
// ---------------------------------------------------------------------------
__device__ __forceinline__ uint32_t smem_u32(const void* p) {
    uint32_t a;
    asm("{ .reg .u64 t; cvta.to.shared.u64 t, %1; cvt.u32.u64 %0, t; }"
        : "=r"(a) : "l"(p));
    return a;
}
__device__ __forceinline__ void cp_async16(uint32_t s, const void* g) {
    asm volatile("cp.async.cg.shared.global [%0], [%1], 16;"
                 :: "r"(s), "l"(g));
}
__device__ __forceinline__ void cp_commit() {
    asm volatile("cp.async.commit_group;" ::: "memory");
}
template<int N>
__device__ __forceinline__ void cp_wait() {
    asm volatile("cp.async.wait_group %0;" :: "n"(N) : "memory");
}
__device__ __forceinline__ void ldmatrix_x4(uint32_t& r0, uint32_t& r1,
                                            uint32_t& r2, uint32_t& r3,
                                            uint32_t addr) {
    asm volatile("ldmatrix.sync.aligned.m8n8.x4.shared.b16 {%0,%1,%2,%3}, [%4];"
                 : "=r"(r0), "=r"(r1), "=r"(r2), "=r"(r3) : "r"(addr));
}
__device__ __forceinline__ void mma_f16(float* c, const uint32_t* a,
                                        const uint32_t* b) {
    asm volatile(
        "mma.sync.aligned.m16n8k16.row.col.f32.f16.f16.f32 "
        "{%0,%1,%2,%3}, {%4,%5,%6,%7}, {%8,%9}, {%0,%1,%2,%3};"
        : "+f"(c[0]), "+f"(c[1]), "+f"(c[2]), "+f"(c[3])
        : "r"(a[0]), "r"(a[1]), "r"(a[2]), "r"(a[3]),
          "r"(b[0]), "r"(b[1]));
}

// ---------------------------------------------------------------------------
// Fused weight convert fp32 -> half (all 4 weights in one launch)
// ---------------------------------------------------------------------------
#define WN1 (QKVC*CCH)
#define WN2 (CCH*CCH)
#define WN3 (HIDN*CCH)
#define WN4 (CCH*HIDN)
#define WNT (WN1+WN2+WN3+WN4)

__global__ __launch_bounds__(256) void convw4_kernel(
    const float* __restrict__ s1, const float* __restrict__ s2,
    const float* __restrict__ s3, const float* __restrict__ s4,
    __half* __restrict__ d1, __half* __restrict__ d2,
    __half* __restrict__ d3, __half* __restrict__ d4)
{
    int i = blockIdx.x * 256 + threadIdx.x;
    if (i < WN1) { d1[i] = __float2half(s1[i]); return; }
    i -= WN1;
    if (i < WN2) { d2[i] = __float2half(s2[i]); return; }
    i -= WN2;
    if (i < WN3) { d3[i] = __float2half(s3[i]); return; }
    i -= WN3;
    if (i < WN4) d4[i] = __float2half(s4[i]);
}

// ---------------------------------------------------------------------------
// fp16 mma.sync GEMM:  C[M,Nc] = A[M,K] @ Bw[Nc,K]^T
// CTA tile 128x128, BK=64 halves (128B rows, XOR swizzle), 3-stage cp.async.
// 256 threads = 8 warps as 2(M)x4(N); warp tile 64x32 via m16n8k16 + ldmatrix.
// mode: 0 = plain -> half out
//       1 = bias + exact erf GELU -> half out
//       2 = bias + fp32 residual -> float out [N,C]
//       3 = bias + fp32 residual -> float out [B,C,HW] (fused transpose)
// ---------------------------------------------------------------------------
#define OPST   16384                 // bytes per operand tile (128 x 128B)
#define NSTAGE 3
#define GEMM_SMEM (NSTAGE*2*OPST)    // 98304

__global__ __launch_bounds__(256, 2) void gemm_f16_kernel(
    const __half* __restrict__ A, const __half* __restrict__ Bw,
    const float* __restrict__ bias, const float* __restrict__ resid,
    void* __restrict__ Cout, int M, int Nc, int K, int mode)
{
    extern __shared__ char smem[];
    uint32_t sb = smem_u32(smem);

    int tid    = threadIdx.x;
    int wid    = tid >> 5;
    int lane   = tid & 31;
    int warp_m = wid & 1;
    int warp_n = wid >> 1;
    int m0     = blockIdx.x * 128;
    int n0     = blockIdx.y * 128;

    const __half* Ab = A  + (size_t)m0 * K;
    const __half* Bb = Bw + (size_t)n0 * K;
    const int NCH = K >> 6;

    int gid = lane >> 2;
    int tig = lane & 3;

    int arow_l = (lane & 7) + ((lane >> 3) & 1) * 8;
    int asub   = (lane >> 4) & 1;
    int brow_l = (lane & 7) + ((lane >> 4) & 1) * 8;
    int bsub   = (lane >> 3) & 1;

    float acc[4][4][4];
    #pragma unroll
    for (int i = 0; i < 4; i++)
        #pragma unroll
        for (int j = 0; j < 4; j++)
            #pragma unroll
            for (int q = 0; q < 4; q++) acc[i][j][q] = 0.f;

    auto load_chunk = [&](int kc, int st) {
        uint32_t abase = sb + st * (2*OPST);
        uint32_t bbase = abase + OPST;
        int kh = kc << 6;
        #pragma unroll
        for (int r = 0; r < 8; r++) {
            int idx = tid + r * 256;
            int op  = idx >> 10;
            int wi  = idx & 1023;
            int row = wi >> 3;
            int g   = wi & 7;
            uint32_t dst = (op ? bbase : abase)
                         + (uint32_t)(row * 128 + ((g ^ (row & 7)) << 4));
            const __half* src = (op ? Bb : Ab) + (size_t)row * K + kh + g * 8;
            cp_async16(dst, src);
        }
        cp_commit();
    };

    load_chunk(0, 0);
    load_chunk(1, 1);

    for (int i = 0; i < NCH; i++) {
        if (i < NCH - 1) cp_wait<1>(); else cp_wait<0>();
        __syncthreads();

        int st = i % NSTAGE;
        uint32_t abase = sb + st * (2*OPST);
        uint32_t bbase = abase + OPST;

        #pragma unroll
        for (int ks = 0; ks < 4; ks++) {
            uint32_t afr[4][4];
            #pragma unroll
            for (int mf = 0; mf < 4; mf++) {
                int row = warp_m * 64 + mf * 16 + arow_l;
                int gph = ((ks * 2 + asub) ^ (row & 7));
                ldmatrix_x4(afr[mf][0], afr[mf][1], afr[mf][2], afr[mf][3],
                            abase + (uint32_t)(row * 128 + gph * 16));
            }
            uint32_t bfr[4][2];
            #pragma unroll
            for (int pf = 0; pf < 2; pf++) {
                int row = warp_n * 32 + pf * 16 + brow_l;
                int gph = ((ks * 2 + bsub) ^ (row & 7));
                ldmatrix_x4(bfr[2*pf][0], bfr[2*pf][1],
                            bfr[2*pf+1][0], bfr[2*pf+1][1],
                            bbase + (uint32_t)(row * 128 + gph * 16));
            }
            #pragma unroll
            for (int mf = 0; mf < 4; mf++)
                #pragma unroll
                for (int nf = 0; nf < 4; nf++)
                    mma_f16(acc[mf][nf], afr[mf], bfr[nf]);
        }

        if (i + 2 < NCH) load_chunk(i + 2, (i + 2) % NSTAGE);
    }

    // ---------------- epilogue ----------------
    if (mode == 3) {
        __syncthreads();
        float* tile = (float*)smem;            // [128][129]
        #pragma unroll
        for (int mf = 0; mf < 4; mf++) {
            #pragma unroll
            for (int nf = 0; nf < 4; nf++) {
                int rl = warp_m * 64 + mf * 16 + gid;
                int cl = warp_n * 32 + nf * 8 + tig * 2;
                #pragma unroll
                for (int half_i = 0; half_i < 2; half_i++) {
                    int r = rl + half_i * 8;
                    size_t rr = (size_t)(m0 + r);
                    float v0 = acc[mf][nf][half_i * 2 + 0] + bias[n0 + cl];
                    float v1 = acc[mf][nf][half_i * 2 + 1] + bias[n0 + cl + 1];
                    float2 rv = *(const float2*)&resid[rr * Nc + n0 + cl];
                    v0 += rv.x; v1 += rv.y;
                    tile[r * 129 + cl    ] = v0;
                    tile[r * 129 + cl + 1] = v1;
                }
            }
        }
        __syncthreads();
        float* out = (float*)Cout;
        #pragma unroll
        for (int cs = 0; cs < 16; cs++) {
            int c = wid * 16 + cs;
            #pragma unroll
            for (int rs = 0; rs < 4; rs++) {
                int r  = rs * 32 + lane;
                int rr = m0 + r;
                int b  = rr / HWSZ;
                int s  = rr - b * HWSZ;
                out[((size_t)b * CCH + n0 + c) * HWSZ + s] = tile[r * 129 + c];
            }
        }
        return;
    }

    #pragma unroll
    for (int mf = 0; mf < 4; mf++) {
        #pragma unroll
        for (int nf = 0; nf < 4; nf++) {
            int row = m0 + warp_m * 64 + mf * 16 + gid;
            int col = n0 + warp_n * 32 + nf * 8 + tig * 2;
            #pragma unroll
            for (int half_i = 0; half_i < 2; half_i++) {
                size_t rr = (size_t)(row + half_i * 8);
                float v0 = acc[mf][nf][half_i * 2 + 0];
                float v1 = acc[mf][nf][half_i * 2 + 1];
                if (bias) { v0 += bias[col]; v1 += bias[col + 1]; }
                if (mode == 1) {
                    v0 = 0.5f * v0 * (1.0f + erff(v0 * 0.7071067811865476f));
                    v1 = 0.5f * v1 * (1.0f + erff(v1 * 0.7071067811865476f));
                }
                if (mode == 2) {
                    float2 rv = *(const float2*)&resid[rr * Nc + col];
                    v0 += rv.x; v1 += rv.y;
                    float2 o; o.x = v0; o.y = v1;
                    *(float2*)&((float*)Cout)[rr * Nc + col] = o;
                } else {
                    __half2 o = __floats2half2_rn(v0, v1);
                    *(__half2*)&((__half*)Cout)[rr * Nc + col] = o;
                }
            }
        }
    }
}

// ---------------------------------------------------------------------------
// LN1: x [B,C,H,W] -> xn [N,C] (half) + xpT [N,C] (fp32)
// ---------------------------------------------------------------------------
__global__ __launch_bounds__(256) void ln1_kernel(
    const float* __restrict__ x, const float* __restrict__ gam,
    const float* __restrict__ bet, __half* __restrict__ xn,
    float* __restrict__ xpT)
{
    const int TPB = 28;
    __shared__ float s[CCH*TPB];
    __shared__ float ps[9*TPB];
    __shared__ float pq[9*TPB];
    __shared__ float s_mean[TPB];
    __shared__ float s_rstd[TPB];

    int tid = threadIdx.x;
    int x0  = blockIdx.x * TPB;
    int y   = blockIdx.y;
    int b   = blockIdx.z;

    for (int idx = tid; idx < CCH*TPB; idx += 256) {
        int c = idx / TPB;
        int t = idx % TPB;
        s[idx] = x[(((size_t)b*CCH + c)*HH + y)*WW + x0 + t];
    }
    __syncthreads();

    if (tid < 9*TPB) {
        int sub = tid / TPB;
        int t   = tid % TPB;
        float sm = 0.f, sq = 0.f;
        for (int c = sub; c < CCH; c += 9) {
            float v = s[c*TPB + t];
            sm += v; sq += v*v;
        }
        ps[sub*TPB + t] = sm;
        pq[sub*TPB + t] = sq;
    }
    __syncthreads();
    if (tid < TPB) {
        float sm = 0.f, sq = 0.f;
        #pragma unroll
        for (int sub = 0; sub < 9; sub++) { sm += ps[sub*TPB + tid]; sq += pq[sub*TPB + tid]; }
        float mu  = sm * (1.f/CCH);
        float var = sq * (1.f/CCH) - mu*mu;
        s_mean[tid] = mu;
        s_rstd[tid] = rsqrtf(var + EPSLN);
    }
    __syncthreads();

    for (int idx = tid; idx < CCH*TPB; idx += 256) {
        int t = idx / CCH;
        int c = idx % CCH;
        float v = s[c*TPB + t];
        size_t n = (size_t)b*HWSZ + (size_t)y*WW + (x0 + t);
        xpT[n*CCH + c] = v;
        xn [n*CCH + c] =
            __float2half((v - s_mean[t]) * s_rstd[t] * gam[c] + bet[c]);
    }
}

// ---------------------------------------------------------------------------
// Multi-dilation 3x3 local attention + fused "+xn" residual.
// One warp = one head x TWO adjacent tokens (2p, 2p+1 along W; WW even so
// pairs never cross rows). 16 lanes per token, one __half2 (2 dims) per lane.
// Butterfly offsets 8,4,2,1 stay inside each half-warp. 32-bit addressing;
// neighbor deltas are warp-uniform. OOB -> logit 0, v 0 (zero-pad unfold).
// ---------------------------------------------------------------------------
__global__ __launch_bounds__(384) void attn_kernel(
    const __half* __restrict__ qkv, const __half* __restrict__ xn,
    __half* __restrict__ att)
{
    int n    = blockIdx.x * 2 + ((threadIdx.x >> 4) & 1);
    int w    = threadIdx.x >> 5;      // head 0..11
    int l16  = threadIdx.x & 15;      // dim-pair index

    int b    = n / HWSZ;
    int rem  = n - b * HWSZ;
    int y    = rem / WW;
    int xx   = rem - y * WW;

    int dil  = (w >> 2) + 1;          // DILS = (1,2,3)
    int c0   = w * HDIM;

    const float scale = 0.17677669529663687f;   // 32^-0.5

    uint32_t base = (uint32_t)n * QKVC + c0 + 2 * l16;

    float2 qf = __half22float2(*(const __half2*)(qkv + base));

    float    logit[9];
    int      delta[9];
    unsigned okm = 0;
    #pragma unroll
    for (int e = 0; e < 9; e++) {
        int ki = e / 3, kj = e % 3;
        int ny = y  + (ki - 1) * dil;
        int nx = xx + (kj - 1) * dil;
        bool ok = ((unsigned)ny < HH) && ((unsigned)nx < WW);
        delta[e] = ((ki - 1) * WW + (kj - 1)) * dil * QKVC;
        float p = 0.f;
        if (ok) {
            okm |= (1u << e);
            float2 kf = __half22float2(
                *(const __half2*)(qkv + (int)base + CCH + delta[e]));
            p = qf.x * kf.x + qf.y * kf.y;
        }
        #pragma unroll
        for (int off = 8; off > 0; off >>= 1)
            p += __shfl_xor_sync(0xffffffffu, p, off);
        logit[e] = p * scale;
    }

    float mx = logit[0];
    #pragma unroll
    for (int e = 1; e < 9; e++) mx = fmaxf(mx, logit[e]);
    float pe[9];
    float sum = 0.f;
    #pragma unroll
    for (int e = 0; e < 9; e++) { pe[e] = __expf(logit[e] - mx); sum += pe[e]; }
    float inv = 1.f / sum;

    float ox = 0.f, oy = 0.f;
    #pragma unroll
    for (int e = 0; e < 9; e++) {
        if (okm & (1u << e)) {
            float2 vf = __half22float2(
                *(const __half2*)(qkv + (int)base + 2*CCH + delta[e]));
            float p = pe[e] * inv;
            ox = fmaf(p, vf.x, ox);
            oy = fmaf(p, vf.y, oy);
        }
    }

    uint32_t obase = (uint32_t)n * CCH + c0 + 2 * l16;
    float2 xf = __half22float2(*(const __half2*)(xn + obase));
    *(__half2*)(att + obase) = __floats2half2_rn(ox + xf.x, oy + xf.y);
}

// ---------------------------------------------------------------------------
// LN2: fp32 in -> half out
// ---------------------------------------------------------------------------
__global__ __launch_bounds__(128) void ln2_kernel(
    const float* __restrict__ in, const float* __restrict__ gam,
    const float* __restrict__ bet, __half* __restrict__ out)
{
    __shared__ float rs[4], rq[4];
    __shared__ float s_mu, s_rstd;
    int n   = blockIdx.x;
    int tid = threadIdx.x;
    const float* row = in + (size_t)n * CCH;

    float v0 = row[tid];
    float v1 = row[tid + 128];
    float v2 = row[tid + 256];
    float sm = v0 + v1 + v2;
    float sq = v0*v0 + v1*v1 + v2*v2;
    #pragma unroll
    for (int off = 16; off > 0; off >>= 1) {
        sm += __shfl_xor_sync(0xffffffffu, sm, off);
        sq += __shfl_xor_sync(0xffffffffu, sq, off);
    }
    int wid = tid >> 5, lane = tid & 31;
    if (lane == 0) { rs[wid] = sm; rq[wid] = sq; }
    __syncthreads();
    if (tid == 0) {
        float tsm = rs[0]+rs[1]+rs[2]+rs[3];
        float tsq = rq[0]+rq[1]+rq[2]+rq[3];
        float mu  = tsm * (1.f/CCH);
        float var = tsq * (1.f/CCH) - mu*mu;
        s_mu = mu;
        s_rstd = rsqrtf(var + EPSLN);
    }
    __syncthreads();
    float mu = s_mu, rstd = s_rstd;
    __half* orow = out + (size_t)n * CCH;
    orow[tid      ] = __float2half((v0 - mu) * rstd * gam[tid      ] + bet[tid      ]);
    orow[tid + 128] = __float2half((v1 - mu) * rstd * gam[tid + 128] + bet[tid + 128]);
    orow[tid + 256] = __float2half((v2 - mu) * rstd * gam[tid + 256] + bet[tid + 256]);
}

// ---------------------------------------------------------------------------
// kernel_launch
// ---------------------------------------------------------------------------
extern "C" void kernel_launch(void* const* d_in, const int* in_sizes, int n_in,
                              void* d_out, int out_size)
{
    const float* x      = (const float*)d_in[0];
    const float* qkv_w  = (const float*)d_in[1];
    const float* proj_w = (const float*)d_in[2];
    const float* proj_b = (const float*)d_in[3];
    const float* n1_g   = (const float*)d_in[4];
    const float* n1_b   = (const float*)d_in[5];
    const float* n2_g   = (const float*)d_in[6];
    const float* n2_b   = (const float*)d_in[7];
    const float* fc1_w  = (const float*)d_in[8];
    const float* fc1_b  = (const float*)d_in[9];
    const float* fc2_w  = (const float*)d_in[10];
    const float* fc2_b  = (const float*)d_in[11];
    float* out = (float*)d_out;

    __half *xn, *qkv, *att, *x2, *h, *wq, *wp, *w1, *w2;
    float *xpT, *xpb;
    cudaGetSymbolAddress((void**)&xn,  g_xn);
    cudaGetSymbolAddress((void**)&xpT, g_xpT);
    cudaGetSymbolAddress((void**)&qkv, g_qkv);
    cudaGetSymbolAddress((void**)&att, g_att);
    cudaGetSymbolAddress((void**)&xpb, g_xpb);
    cudaGetSymbolAddress((void**)&x2,  g_x2);
    cudaGetSymbolAddress((void**)&h,   g_h);
    cudaGetSymbolAddress((void**)&wq,  g_wq);
    cudaGetSymbolAddress((void**)&wp,  g_wp);
    cudaGetSymbolAddress((void**)&w1,  g_w1);
    cudaGetSymbolAddress((void**)&w2,  g_w2);

    cudaFuncSetAttribute(gemm_f16_kernel,
                         cudaFuncAttributeMaxDynamicSharedMemorySize, GEMM_SMEM);

    // 0. convert all weights to half (single launch)
    convw4_kernel<<<(WNT + 255)/256, 256>>>(qkv_w, proj_w, fc1_w, fc2_w,
                                            wq, wp, w1, w2);

    // 1. LN1 + NCHW->NHWC transpose
    ln1_kernel<<<dim3(2, HH, BATCH), 256>>>(x, n1_g, n1_b, xn, xpT);

    // 2. QKV: [N,384] @ [1152,384]^T -> half
    gemm_f16_kernel<<<dim3(NTOK/128, QKVC/128), 256, GEMM_SMEM>>>(
        xn, wq, nullptr, nullptr, qkv, NTOK, QKVC, CCH, 0);

    // 3. attention + xn residual -> half (2 tokens per block-pair warp)
    attn_kernel<<<NTOK/2, 384>>>(qkv, xn, att);

    // 4. proj + bias + residual(xpT) -> fp32 [N,C]
    gemm_f16_kernel<<<dim3(NTOK/128, CCH/128), 256, GEMM_SMEM>>>(
        att, wp, proj_b, xpT, xpb, NTOK, CCH, CCH, 2);

    // 5. LN2 -> half
    ln2_kernel<<<NTOK, 128>>>(xpb, n2_g, n2_b, x2);

    // 6. fc1 + bias + exact GELU -> half
    gemm_f16_kernel<<<dim3(NTOK/128, HIDN/128), 256, GEMM_SMEM>>>(
        x2, w1, fc1_b, nullptr, h, NTOK, HIDN, CCH, 1);

    // 7. fc2 + bias + residual(xpb) -> fp32 [B,C,HW] (fused transpose)
    gemm_f16_kernel<<<dim3(NTOK/128, CCH/128), 256, GEMM_SMEM>>>(
        h, w2, fc2_b, xpb, out, NTOK, CCH, HIDN, 3);
}